// round 2
// baseline (speedup 1.0000x reference)
#include <cuda_runtime.h>
#include <cuda_bf16.h>
#include <math.h>

// Problem constants
#define BATCH 2
#define SEQ   2048
#define EMB   1024
#define HEADS 16
#define HDIM  64
#define TOK   (BATCH * SEQ)   // 4096

// ---------------- GEMM: C[M,N] = A[M,K] @ W[N,K]^T ----------------
// BM=64, BN=64, BK=32, 256 threads, 4x4 outputs per thread.
#define BM 64
#define BN 64
#define BK 32
#define GPAD 4

__global__ void gemm_xWt_kernel(const float* __restrict__ A,
                                const float* __restrict__ W,
                                float* __restrict__ C,
                                int M, int N, int K) {
    __shared__ float As[BM][BK + GPAD];
    __shared__ float Bs[BN][BK + GPAD];

    const int tid = threadIdx.x;
    const int ty = tid >> 4;      // 0..15
    const int tx = tid & 15;      // 0..15
    const int rowBase = blockIdx.y * BM;
    const int colBase = blockIdx.x * BN;

    float acc[4][4];
#pragma unroll
    for (int i = 0; i < 4; i++)
#pragma unroll
        for (int j = 0; j < 4; j++) acc[i][j] = 0.f;

    for (int kb = 0; kb < K; kb += BK) {
        // Load tiles: 64 rows x 32 cols = 512 float4 each, 256 threads -> 2 iters
#pragma unroll
        for (int v = tid; v < (BM * BK) / 4; v += 256) {
            int r  = v >> 3;          // 8 float4 per row
            int c4 = (v & 7) * 4;
            float4 a = *(const float4*)&A[(size_t)(rowBase + r) * K + kb + c4];
            *(float4*)&As[r][c4] = a;
            float4 b = *(const float4*)&W[(size_t)(colBase + r) * K + kb + c4];
            *(float4*)&Bs[r][c4] = b;
        }
        __syncthreads();

#pragma unroll
        for (int kk = 0; kk < BK; kk++) {
            float ra[4], rb[4];
#pragma unroll
            for (int i = 0; i < 4; i++) ra[i] = As[ty * 4 + i][kk];
#pragma unroll
            for (int j = 0; j < 4; j++) rb[j] = Bs[tx * 4 + j][kk];
#pragma unroll
            for (int i = 0; i < 4; i++)
#pragma unroll
                for (int j = 0; j < 4; j++) acc[i][j] += ra[i] * rb[j];
        }
        __syncthreads();
    }

#pragma unroll
    for (int i = 0; i < 4; i++) {
        float4 v = make_float4(acc[i][0], acc[i][1], acc[i][2], acc[i][3]);
        *(float4*)&C[(size_t)(rowBase + ty * 4 + i) * N + colBase + tx * 4] = v;
    }
}

// ---------------- Attention (causal, online softmax) ----------------
// Per block: one (batch, head, 64-query tile). 256 threads:
//   thread t -> query row r = t/4, column/dim group g = t%4 (16 cols each).
// Shared tiles 64x64 padded to 68 floats/row. Dynamic smem: 4 * 64*68*4 = 69632 B.
#define APAD 4
#define AW   (HDIM + APAD)   // 68
#define ATTN_SMEM (4 * 64 * AW * 4)

__global__ void attn_kernel(const float* __restrict__ Qg,
                            const float* __restrict__ Kg,
                            const float* __restrict__ Vg,
                            float* __restrict__ Og) {
    extern __shared__ float sm[];
    float (*Qs)[AW] = (float(*)[AW])sm;
    float (*Ks)[AW] = Qs + 64;
    float (*Vs)[AW] = Ks + 64;
    float (*Ps)[AW] = Vs + 64;

    const int tid = threadIdx.x;
    const int r = tid >> 2;     // query row in tile: 0..63
    const int g = tid & 3;      // group: 0..3
    const int qt = blockIdx.x;  // query tile: 0..31
    const int h  = blockIdx.y;
    const int b  = blockIdx.z;

    const size_t base = (size_t)b * SEQ * EMB + (size_t)h * HDIM;
    const float* Qp = Qg + base;
    const float* Kp = Kg + base;
    const float* Vp = Vg + base;
    float* Op = Og + base;

    // Load Q tile: 64 rows x 64 dims = 1024 float4, 4 iters
#pragma unroll
    for (int v = tid; v < 64 * 16; v += 256) {
        int rr = v >> 4, c4 = (v & 15) * 4;
        *(float4*)&Qs[rr][c4] = *(const float4*)&Qp[(size_t)(qt * 64 + rr) * EMB + c4];
    }

    float m = -1e30f;
    float l = 0.f;
    float acc[16];
#pragma unroll
    for (int j = 0; j < 16; j++) acc[j] = 0.f;

    const float scale = 0.125f;  // 1/sqrt(64)
    const int qg = qt * 64 + r;

    for (int kt = 0; kt <= qt; kt++) {
        // Load K and V tiles
        __syncthreads();
#pragma unroll
        for (int v = tid; v < 64 * 16; v += 256) {
            int rr = v >> 4, c4 = (v & 15) * 4;
            *(float4*)&Ks[rr][c4] = *(const float4*)&Kp[(size_t)(kt * 64 + rr) * EMB + c4];
            *(float4*)&Vs[rr][c4] = *(const float4*)&Vp[(size_t)(kt * 64 + rr) * EMB + c4];
        }
        __syncthreads();

        // Scores: s[j] = Q[r,:] . K[g*16+j,:]
        float s[16];
#pragma unroll
        for (int j = 0; j < 16; j++) s[j] = 0.f;
#pragma unroll
        for (int e = 0; e < HDIM; e++) {
            float q = Qs[r][e];
#pragma unroll
            for (int j = 0; j < 16; j++) s[j] += q * Ks[g * 16 + j][e];
        }

        // Scale + causal mask (only diagonal tile has masked entries)
#pragma unroll
        for (int j = 0; j < 16; j++) {
            int kg = kt * 64 + g * 16 + j;
            float sv = s[j] * scale;
            s[j] = (kg > qg) ? -1e30f : sv;
        }

        // Row max across the 4 threads of this row
        float mt = s[0];
#pragma unroll
        for (int j = 1; j < 16; j++) mt = fmaxf(mt, s[j]);
        mt = fmaxf(mt, __shfl_xor_sync(0xffffffffu, mt, 1));
        mt = fmaxf(mt, __shfl_xor_sync(0xffffffffu, mt, 2));

        float mnew = fmaxf(m, mt);
        float corr = __expf(m - mnew);

        float psum = 0.f;
#pragma unroll
        for (int j = 0; j < 16; j++) {
            float p = __expf(s[j] - mnew);
            Ps[r][g * 16 + j] = p;
            psum += p;
        }
        psum += __shfl_xor_sync(0xffffffffu, psum, 1);
        psum += __shfl_xor_sync(0xffffffffu, psum, 2);

        l = l * corr + psum;
        m = mnew;
#pragma unroll
        for (int j = 0; j < 16; j++) acc[j] *= corr;

        __syncthreads();  // Ps fully written

        // O update: acc[j] += sum_k P[r,k] * V[k, g*16+j]
#pragma unroll
        for (int k = 0; k < 64; k++) {
            float p = Ps[r][k];
#pragma unroll
            for (int j = 0; j < 16; j++) acc[j] += p * Vs[k][g * 16 + j];
        }
    }

    float inv = 1.f / l;
#pragma unroll
    for (int j = 0; j < 16; j++) acc[j] *= inv;

    float* op = &Op[(size_t)qg * EMB + g * 16];
#pragma unroll
    for (int j4 = 0; j4 < 4; j4++) {
        float4 v = make_float4(acc[j4 * 4 + 0], acc[j4 * 4 + 1],
                               acc[j4 * 4 + 2], acc[j4 * 4 + 3]);
        *(float4*)&op[j4 * 4] = v;
    }
}

// ---------------- Scratch (device globals; no allocation allowed) ----------------
__device__ float g_Q[TOK * EMB];
__device__ float g_K[TOK * EMB];
__device__ float g_V[TOK * EMB];
__device__ float g_A[TOK * EMB];

extern "C" void kernel_launch(void* const* d_in, const int* in_sizes, int n_in,
                              void* d_out, int out_size) {
    const float* x  = (const float*)d_in[0];
    // d_in[1] is the causal mask; ignored (causality is hard-coded).
    const float* Wq = (const float*)d_in[2];
    const float* Wk = (const float*)d_in[3];
    const float* Wv = (const float*)d_in[4];
    const float* Wo = (const float*)d_in[5];
    float* out = (float*)d_out;

    float *dQ, *dK, *dV, *dA;
    cudaGetSymbolAddress((void**)&dQ, g_Q);
    cudaGetSymbolAddress((void**)&dK, g_K);
    cudaGetSymbolAddress((void**)&dV, g_V);
    cudaGetSymbolAddress((void**)&dA, g_A);

    dim3 gemmGrid(EMB / BN, TOK / BM);  // (16, 64)

    gemm_xWt_kernel<<<gemmGrid, 256>>>(x, Wq, dQ, TOK, EMB, EMB);
    gemm_xWt_kernel<<<gemmGrid, 256>>>(x, Wk, dK, TOK, EMB, EMB);
    gemm_xWt_kernel<<<gemmGrid, 256>>>(x, Wv, dV, TOK, EMB, EMB);

    cudaFuncSetAttribute(attn_kernel, cudaFuncAttributeMaxDynamicSharedMemorySize,
                         ATTN_SMEM);
    dim3 attnGrid(SEQ / 64, HEADS, BATCH);  // (32, 16, 2)
    attn_kernel<<<attnGrid, 256, ATTN_SMEM>>>(dQ, dK, dV, dA);

    gemm_xWt_kernel<<<gemmGrid, 256>>>(dA, Wo, out, TOK, EMB, EMB);
}

// round 4
// speedup vs baseline: 1.4740x; 1.4740x over previous
#include <cuda_runtime.h>
#include <cuda_bf16.h>
#include <cstdint>
#include <math.h>

// Problem constants
#define BATCH 2
#define SEQ   2048
#define EMB   1024
#define HEADS 16
#define HDIM  64
#define TOK   (BATCH * SEQ)   // 4096

// ======================= PTX helpers (baseline sm_80-era ISA only) =======================
__device__ __forceinline__ uint32_t smem_u32(const void* p) {
    uint32_t a;
    asm("{ .reg .u64 t; cvta.to.shared.u64 t, %1; cvt.u32.u64 %0, t; }"
        : "=r"(a) : "l"(p));
    return a;
}

#define LDSM_X4(r, a) \
    asm volatile("ldmatrix.sync.aligned.m8n8.x4.shared.b16 {%0,%1,%2,%3}, [%4];" \
                 : "=r"((r)[0]), "=r"((r)[1]), "=r"((r)[2]), "=r"((r)[3]) : "r"(a))

#define LDSM_X2(r, a) \
    asm volatile("ldmatrix.sync.aligned.m8n8.x2.shared.b16 {%0,%1}, [%2];" \
                 : "=r"((r)[0]), "=r"((r)[1]) : "r"(a))

#define MMA16816(d, a, b) \
    asm volatile("mma.sync.aligned.m16n8k16.row.col.f32.bf16.bf16.f32 " \
                 "{%0,%1,%2,%3}, {%4,%5,%6,%7}, {%8,%9}, {%0,%1,%2,%3};" \
                 : "+f"((d)[0]), "+f"((d)[1]), "+f"((d)[2]), "+f"((d)[3]) \
                 : "r"((a)[0]), "r"((a)[1]), "r"((a)[2]), "r"((a)[3]), \
                   "r"((b)[0]), "r"((b)[1]))

#define CP_ASYNC16(saddr, gaddr) \
    asm volatile("cp.async.cg.shared.global [%0], [%1], 16;" :: "r"(saddr), "l"(gaddr))
#define CP_COMMIT() asm volatile("cp.async.commit_group;" ::: "memory")
#define CP_WAIT1() asm volatile("cp.async.wait_group 1;" ::: "memory")
#define CP_WAIT0() asm volatile("cp.async.wait_group 0;" ::: "memory")

// ======================= fp32 -> (bf16 hi, bf16 lo) split =======================
__global__ void cvt_split_kernel(const float* __restrict__ in,
                                 __nv_bfloat16* __restrict__ hi,
                                 __nv_bfloat16* __restrict__ lo, int n4) {
    int i = blockIdx.x * blockDim.x + threadIdx.x;
    if (i >= n4) return;
    float4 v = *(const float4*)(in + i * 4);
    __nv_bfloat16 h0 = __float2bfloat16(v.x);
    __nv_bfloat16 h1 = __float2bfloat16(v.y);
    __nv_bfloat16 h2 = __float2bfloat16(v.z);
    __nv_bfloat16 h3 = __float2bfloat16(v.w);
    __nv_bfloat16 l0 = __float2bfloat16(v.x - __bfloat162float(h0));
    __nv_bfloat16 l1 = __float2bfloat16(v.y - __bfloat162float(h1));
    __nv_bfloat16 l2 = __float2bfloat16(v.z - __bfloat162float(h2));
    __nv_bfloat16 l3 = __float2bfloat16(v.w - __bfloat162float(h3));
    *(__nv_bfloat162*)(hi + i * 4)     = __halves2bfloat162(h0, h1);
    *(__nv_bfloat162*)(hi + i * 4 + 2) = __halves2bfloat162(h2, h3);
    *(__nv_bfloat162*)(lo + i * 4)     = __halves2bfloat162(l0, l1);
    *(__nv_bfloat162*)(lo + i * 4 + 2) = __halves2bfloat162(l2, l3);
}

// ======================= mma.sync split-bf16 GEMM =======================
// C[M,N] = A[M,K] @ W[N,K]^T via A_hi*B_hi + A_hi*B_lo + A_lo*B_hi.
// CTA tile 128x128, KT=64, 8 warps (2x4), warp tile 64x32.
// SMEM: SW128-swizzled K-major tiles, cp.async double buffered.
#define MT 128
#define NT 128
#define KT 64
#define NKTILE (EMB / KT)            // 16
#define TILE_BYTES (128 * KT * 2)    // 16KB (128 rows x 128B)
#define STAGE_BYTES (4 * TILE_BYTES) // Ahi, Alo, Bhi, Blo = 64KB
#define GEMM_SMEM (2 * STAGE_BYTES)  // 128KB

__global__ void __launch_bounds__(256, 1)
gemm_mma_kernel(const __nv_bfloat16* __restrict__ Ahi,
                const __nv_bfloat16* __restrict__ Alo,
                const __nv_bfloat16* __restrict__ Bhi,
                const __nv_bfloat16* __restrict__ Blo,
                float* __restrict__ C) {
    extern __shared__ char sm[];
    const uint32_t smb = smem_u32(sm);

    const int tid = threadIdx.x;
    const int lane = tid & 31;
    const int wid = tid >> 5;
    const int wm = wid >> 2;          // 0..1 (64 rows each)
    const int wn = wid & 3;           // 0..3 (32 cols each)
    const int rowBase = blockIdx.y * MT;
    const int colBase = blockIdx.x * NT;

    float acc[4][4][4];
#pragma unroll
    for (int mi = 0; mi < 4; mi++)
#pragma unroll
        for (int ni = 0; ni < 4; ni++)
#pragma unroll
            for (int j = 0; j < 4; j++) acc[mi][ni][j] = 0.f;

    // ---- stage loader: 4 arrays x 1024 16B-chunks, SW128 swizzle ----
    auto load_stage = [&](int s, int kt) {
        const int k0 = kt * KT;
        const __nv_bfloat16* bases[4] = {Ahi, Alo, Bhi, Blo};
        const int rb[4] = {rowBase, rowBase, colBase, colBase};
#pragma unroll
        for (int arr = 0; arr < 4; arr++) {
            uint32_t sb = smb + s * STAGE_BYTES + arr * TILE_BYTES;
#pragma unroll
            for (int it = 0; it < 4; it++) {
                int idx = tid + it * 256;    // 0..1023
                int row = idx >> 3;          // 0..127
                int ch  = idx & 7;           // 16B chunk in 128B row
                uint32_t soff = sb + row * 128 + ((ch ^ (row & 7)) * 16);
                const void* g = bases[arr] + (size_t)(rb[arr] + row) * EMB + k0 + ch * 8;
                CP_ASYNC16(soff, g);
            }
        }
        CP_COMMIT();
    };

    auto compute_stage = [&](int s) {
        const uint32_t sah = smb + s * STAGE_BYTES + 0 * TILE_BYTES;
        const uint32_t sal = smb + s * STAGE_BYTES + 1 * TILE_BYTES;
        const uint32_t sbh = smb + s * STAGE_BYTES + 2 * TILE_BYTES;
        const uint32_t sbl = smb + s * STAGE_BYTES + 3 * TILE_BYTES;
#pragma unroll
        for (int ks = 0; ks < 4; ks++) {
            uint32_t ahi[4][4], alo[4][4];
#pragma unroll
            for (int mi = 0; mi < 4; mi++) {
                int row = wm * 64 + mi * 16 + (lane & 15);
                int ch = ks * 2 + (lane >> 4);
                uint32_t off = row * 128 + ((ch ^ (row & 7)) * 16);
                LDSM_X4(ahi[mi], sah + off);
                LDSM_X4(alo[mi], sal + off);
            }
            uint32_t bhi[4][2], blo[4][2];
#pragma unroll
            for (int ni = 0; ni < 4; ni++) {
                int row = wn * 32 + ni * 8 + (lane & 7);
                int ch = ks * 2 + ((lane >> 3) & 1);
                uint32_t off = row * 128 + ((ch ^ (row & 7)) * 16);
                LDSM_X2(bhi[ni], sbh + off);
                LDSM_X2(blo[ni], sbl + off);
            }
#pragma unroll
            for (int mi = 0; mi < 4; mi++)
#pragma unroll
                for (int ni = 0; ni < 4; ni++) {
                    MMA16816(acc[mi][ni], ahi[mi], bhi[ni]);
                    MMA16816(acc[mi][ni], ahi[mi], blo[ni]);
                    MMA16816(acc[mi][ni], alo[mi], bhi[ni]);
                }
        }
    };

    // ---- pipeline: 2-stage double buffer ----
    load_stage(0, 0);
    load_stage(1, 1);

    for (int t = 0; t < NKTILE; t++) {
        if (t < NKTILE - 2) CP_WAIT1(); else CP_WAIT0();
        __syncthreads();
        compute_stage(t & 1);
        __syncthreads();
        if (t + 2 < NKTILE) load_stage(t & 1, t + 2);
    }

    // ---- epilogue: fp32 accumulators straight to C ----
#pragma unroll
    for (int mi = 0; mi < 4; mi++) {
#pragma unroll
        for (int ni = 0; ni < 4; ni++) {
            int row = rowBase + wm * 64 + mi * 16 + (lane >> 2);
            int col = colBase + wn * 32 + ni * 8 + (lane & 3) * 2;
            *(float2*)&C[(size_t)row * EMB + col] =
                make_float2(acc[mi][ni][0], acc[mi][ni][1]);
            *(float2*)&C[(size_t)(row + 8) * EMB + col] =
                make_float2(acc[mi][ni][2], acc[mi][ni][3]);
        }
    }
}

// ======================= Attention (causal, online softmax, fp32) =======================
#define APAD 4
#define AW   (HDIM + APAD)   // 68
#define ATTN_SMEM (4 * 64 * AW * 4)

__global__ void attn_kernel(const float* __restrict__ Qg,
                            const float* __restrict__ Kg,
                            const float* __restrict__ Vg,
                            float* __restrict__ Og) {
    extern __shared__ float smf[];
    float (*Qs)[AW] = (float(*)[AW])smf;
    float (*Ks)[AW] = Qs + 64;
    float (*Vs)[AW] = Ks + 64;
    float (*Ps)[AW] = Vs + 64;

    const int tid = threadIdx.x;
    const int r = tid >> 2;
    const int g = tid & 3;
    const int qt = blockIdx.x;
    const int h  = blockIdx.y;
    const int b  = blockIdx.z;

    const size_t base = (size_t)b * SEQ * EMB + (size_t)h * HDIM;
    const float* Qp = Qg + base;
    const float* Kp = Kg + base;
    const float* Vp = Vg + base;
    float* Op = Og + base;

#pragma unroll
    for (int v = tid; v < 64 * 16; v += 256) {
        int rr = v >> 4, c4 = (v & 15) * 4;
        *(float4*)&Qs[rr][c4] = *(const float4*)&Qp[(size_t)(qt * 64 + rr) * EMB + c4];
    }

    float m = -1e30f;
    float l = 0.f;
    float acc[16];
#pragma unroll
    for (int j = 0; j < 16; j++) acc[j] = 0.f;

    const float scale = 0.125f;
    const int qg = qt * 64 + r;

    for (int kt = 0; kt <= qt; kt++) {
        __syncthreads();
#pragma unroll
        for (int v = tid; v < 64 * 16; v += 256) {
            int rr = v >> 4, c4 = (v & 15) * 4;
            *(float4*)&Ks[rr][c4] = *(const float4*)&Kp[(size_t)(kt * 64 + rr) * EMB + c4];
            *(float4*)&Vs[rr][c4] = *(const float4*)&Vp[(size_t)(kt * 64 + rr) * EMB + c4];
        }
        __syncthreads();

        float s[16];
#pragma unroll
        for (int j = 0; j < 16; j++) s[j] = 0.f;
#pragma unroll
        for (int e = 0; e < HDIM; e++) {
            float q = Qs[r][e];
#pragma unroll
            for (int j = 0; j < 16; j++) s[j] += q * Ks[g * 16 + j][e];
        }

#pragma unroll
        for (int j = 0; j < 16; j++) {
            int kg = kt * 64 + g * 16 + j;
            float sv = s[j] * scale;
            s[j] = (kg > qg) ? -1e30f : sv;
        }

        float mt = s[0];
#pragma unroll
        for (int j = 1; j < 16; j++) mt = fmaxf(mt, s[j]);
        mt = fmaxf(mt, __shfl_xor_sync(0xffffffffu, mt, 1));
        mt = fmaxf(mt, __shfl_xor_sync(0xffffffffu, mt, 2));

        float mnew = fmaxf(m, mt);
        float corr = __expf(m - mnew);

        float psum = 0.f;
#pragma unroll
        for (int j = 0; j < 16; j++) {
            float p = __expf(s[j] - mnew);
            Ps[r][g * 16 + j] = p;
            psum += p;
        }
        psum += __shfl_xor_sync(0xffffffffu, psum, 1);
        psum += __shfl_xor_sync(0xffffffffu, psum, 2);

        l = l * corr + psum;
        m = mnew;
#pragma unroll
        for (int j = 0; j < 16; j++) acc[j] *= corr;

        __syncthreads();

#pragma unroll
        for (int k = 0; k < 64; k++) {
            float p = Ps[r][k];
#pragma unroll
            for (int j = 0; j < 16; j++) acc[j] += p * Vs[k][g * 16 + j];
        }
    }

    float inv = 1.f / l;
#pragma unroll
    for (int j = 0; j < 16; j++) acc[j] *= inv;

    float* op = &Op[(size_t)qg * EMB + g * 16];
#pragma unroll
    for (int j4 = 0; j4 < 4; j4++) {
        float4 v = make_float4(acc[j4 * 4 + 0], acc[j4 * 4 + 1],
                               acc[j4 * 4 + 2], acc[j4 * 4 + 3]);
        *(float4*)&op[j4 * 4] = v;
    }
}

// ======================= Scratch =======================
__device__ float g_Q[TOK * EMB];
__device__ float g_K[TOK * EMB];
__device__ float g_V[TOK * EMB];
__device__ float g_A[TOK * EMB];
__device__ __nv_bfloat16 g_xhi[TOK * EMB], g_xlo[TOK * EMB];
__device__ __nv_bfloat16 g_ahi[TOK * EMB], g_alo[TOK * EMB];
__device__ __nv_bfloat16 g_wqhi[EMB * EMB], g_wqlo[EMB * EMB];
__device__ __nv_bfloat16 g_wkhi[EMB * EMB], g_wklo[EMB * EMB];
__device__ __nv_bfloat16 g_wvhi[EMB * EMB], g_wvlo[EMB * EMB];
__device__ __nv_bfloat16 g_wohi[EMB * EMB], g_wolo[EMB * EMB];

extern "C" void kernel_launch(void* const* d_in, const int* in_sizes, int n_in,
                              void* d_out, int out_size) {
    const float* x  = (const float*)d_in[0];
    const float* Wq = (const float*)d_in[2];
    const float* Wk = (const float*)d_in[3];
    const float* Wv = (const float*)d_in[4];
    const float* Wo = (const float*)d_in[5];
    float* out = (float*)d_out;

    float *dQ, *dK, *dV, *dA;
    cudaGetSymbolAddress((void**)&dQ, g_Q);
    cudaGetSymbolAddress((void**)&dK, g_K);
    cudaGetSymbolAddress((void**)&dV, g_V);
    cudaGetSymbolAddress((void**)&dA, g_A);
    __nv_bfloat16 *xhi, *xlo, *ahi, *alo;
    __nv_bfloat16 *wqhi, *wqlo, *wkhi, *wklo, *wvhi, *wvlo, *wohi, *wolo;
    cudaGetSymbolAddress((void**)&xhi, g_xhi);  cudaGetSymbolAddress((void**)&xlo, g_xlo);
    cudaGetSymbolAddress((void**)&ahi, g_ahi);  cudaGetSymbolAddress((void**)&alo, g_alo);
    cudaGetSymbolAddress((void**)&wqhi, g_wqhi); cudaGetSymbolAddress((void**)&wqlo, g_wqlo);
    cudaGetSymbolAddress((void**)&wkhi, g_wkhi); cudaGetSymbolAddress((void**)&wklo, g_wklo);
    cudaGetSymbolAddress((void**)&wvhi, g_wvhi); cudaGetSymbolAddress((void**)&wvlo, g_wvlo);
    cudaGetSymbolAddress((void**)&wohi, g_wohi); cudaGetSymbolAddress((void**)&wolo, g_wolo);

    static bool attrs_set = false;
    if (!attrs_set) {
        cudaFuncSetAttribute(gemm_mma_kernel, cudaFuncAttributeMaxDynamicSharedMemorySize,
                             GEMM_SMEM);
        cudaFuncSetAttribute(attn_kernel, cudaFuncAttributeMaxDynamicSharedMemorySize,
                             ATTN_SMEM);
        attrs_set = true;
    }

    const int XN4 = TOK * EMB / 4;
    const int WN4 = EMB * EMB / 4;

    cvt_split_kernel<<<(XN4 + 255) / 256, 256>>>(x, xhi, xlo, XN4);
    cvt_split_kernel<<<(WN4 + 255) / 256, 256>>>(Wq, wqhi, wqlo, WN4);
    cvt_split_kernel<<<(WN4 + 255) / 256, 256>>>(Wk, wkhi, wklo, WN4);
    cvt_split_kernel<<<(WN4 + 255) / 256, 256>>>(Wv, wvhi, wvlo, WN4);
    cvt_split_kernel<<<(WN4 + 255) / 256, 256>>>(Wo, wohi, wolo, WN4);

    dim3 gemmGrid(EMB / NT, TOK / MT);   // (8, 32)
    gemm_mma_kernel<<<gemmGrid, 256, GEMM_SMEM>>>(xhi, xlo, wqhi, wqlo, dQ);
    gemm_mma_kernel<<<gemmGrid, 256, GEMM_SMEM>>>(xhi, xlo, wkhi, wklo, dK);
    gemm_mma_kernel<<<gemmGrid, 256, GEMM_SMEM>>>(xhi, xlo, wvhi, wvlo, dV);

    dim3 attnGrid(SEQ / 64, HEADS, BATCH);
    attn_kernel<<<attnGrid, 256, ATTN_SMEM>>>(dQ, dK, dV, dA);

    cvt_split_kernel<<<(XN4 + 255) / 256, 256>>>(dA, ahi, alo, XN4);
    gemm_mma_kernel<<<gemmGrid, 256, GEMM_SMEM>>>(ahi, alo, wohi, wolo, out);
}

// round 6
// speedup vs baseline: 11.5691x; 7.8488x over previous
#include <cuda_runtime.h>
#include <cuda_bf16.h>
#include <cstdint>
#include <math.h>

#define BATCH 2
#define SEQ   2048
#define EMB   1024
#define HEADS 16
#define HDIM  64
#define TOK   (BATCH * SEQ)   // 4096

// ======================= PTX helpers (sm_80-era ISA only) =======================
__device__ __forceinline__ uint32_t smem_u32(const void* p) {
    uint32_t a;
    asm("{ .reg .u64 t; cvta.to.shared.u64 t, %1; cvt.u32.u64 %0, t; }"
        : "=r"(a) : "l"(p));
    return a;
}

#define LDSM_X4(r, a) \
    asm volatile("ldmatrix.sync.aligned.m8n8.x4.shared.b16 {%0,%1,%2,%3}, [%4];" \
                 : "=r"((r)[0]), "=r"((r)[1]), "=r"((r)[2]), "=r"((r)[3]) : "r"(a))

#define LDSM_X4T(r, a) \
    asm volatile("ldmatrix.sync.aligned.m8n8.x4.trans.shared.b16 {%0,%1,%2,%3}, [%4];" \
                 : "=r"((r)[0]), "=r"((r)[1]), "=r"((r)[2]), "=r"((r)[3]) : "r"(a))

#define LDSM_X2(r, a) \
    asm volatile("ldmatrix.sync.aligned.m8n8.x2.shared.b16 {%0,%1}, [%2];" \
                 : "=r"((r)[0]), "=r"((r)[1]) : "r"(a))

#define MMA16816(d, a, b) \
    asm volatile("mma.sync.aligned.m16n8k16.row.col.f32.bf16.bf16.f32 " \
                 "{%0,%1,%2,%3}, {%4,%5,%6,%7}, {%8,%9}, {%0,%1,%2,%3};" \
                 : "+f"((d)[0]), "+f"((d)[1]), "+f"((d)[2]), "+f"((d)[3]) \
                 : "r"((a)[0]), "r"((a)[1]), "r"((a)[2]), "r"((a)[3]), \
                   "r"((b)[0]), "r"((b)[1]))

#define CP_ASYNC16(saddr, gaddr) \
    asm volatile("cp.async.cg.shared.global [%0], [%1], 16;" :: "r"(saddr), "l"(gaddr))
#define CP_COMMIT() asm volatile("cp.async.commit_group;" ::: "memory")
#define CP_WAIT2() asm volatile("cp.async.wait_group 2;" ::: "memory")
#define CP_WAIT1() asm volatile("cp.async.wait_group 1;" ::: "memory")
#define CP_WAIT0() asm volatile("cp.async.wait_group 0;" ::: "memory")

__device__ __forceinline__ uint32_t pack_hi2(float x, float y) {
    __nv_bfloat162 t = __halves2bfloat162(__float2bfloat16(x), __float2bfloat16(y));
    return *(uint32_t*)&t;
}
__device__ __forceinline__ uint32_t pack_lo2(float x, float y) {
    __nv_bfloat16 hx = __float2bfloat16(x), hy = __float2bfloat16(y);
    __nv_bfloat162 t = __halves2bfloat162(__float2bfloat16(x - __bfloat162float(hx)),
                                          __float2bfloat16(y - __bfloat162float(hy)));
    return *(uint32_t*)&t;
}

// ======================= fp32 -> (bf16 hi, bf16 lo) split =======================
__global__ void cvt_split_kernel(const float* __restrict__ in,
                                 __nv_bfloat16* __restrict__ hi,
                                 __nv_bfloat16* __restrict__ lo, int n4) {
    int i = blockIdx.x * blockDim.x + threadIdx.x;
    if (i >= n4) return;
    float4 v = *(const float4*)(in + i * 4);
    *(uint32_t*)(hi + i * 4)     = pack_hi2(v.x, v.y);
    *(uint32_t*)(hi + i * 4 + 2) = pack_hi2(v.z, v.w);
    *(uint32_t*)(lo + i * 4)     = pack_lo2(v.x, v.y);
    *(uint32_t*)(lo + i * 4 + 2) = pack_lo2(v.z, v.w);
}

// ======================= mma.sync split-bf16 GEMM =======================
#define MT 128
#define NT 128
#define KT 64
#define NKTILE (EMB / KT)            // 16
#define TILE_BYTES (128 * KT * 2)    // 16KB
#define STAGE_BYTES (4 * TILE_BYTES) // 64KB
#define GEMM_SMEM (2 * STAGE_BYTES)  // 128KB

template <bool SPLIT>
__global__ void __launch_bounds__(256, 1)
gemm_mma_kernel(const __nv_bfloat16* __restrict__ Ahi,
                const __nv_bfloat16* __restrict__ Alo,
                const __nv_bfloat16* __restrict__ Bhi,
                const __nv_bfloat16* __restrict__ Blo,
                float* __restrict__ C,
                __nv_bfloat16* __restrict__ Chi,
                __nv_bfloat16* __restrict__ Clo) {
    extern __shared__ char sm[];
    const uint32_t smb = smem_u32(sm);

    const int tid = threadIdx.x;
    const int lane = tid & 31;
    const int wid = tid >> 5;
    const int wm = wid >> 2;
    const int wn = wid & 3;
    const int rowBase = blockIdx.y * MT;
    const int colBase = blockIdx.x * NT;

    float acc[4][4][4];
#pragma unroll
    for (int mi = 0; mi < 4; mi++)
#pragma unroll
        for (int ni = 0; ni < 4; ni++)
#pragma unroll
            for (int j = 0; j < 4; j++) acc[mi][ni][j] = 0.f;

    auto load_stage = [&](int s, int kt) {
        const int k0 = kt * KT;
        const __nv_bfloat16* bases[4] = {Ahi, Alo, Bhi, Blo};
        const int rb[4] = {rowBase, rowBase, colBase, colBase};
#pragma unroll
        for (int arr = 0; arr < 4; arr++) {
            uint32_t sb = smb + s * STAGE_BYTES + arr * TILE_BYTES;
#pragma unroll
            for (int it = 0; it < 4; it++) {
                int idx = tid + it * 256;
                int row = idx >> 3;
                int ch  = idx & 7;
                uint32_t soff = sb + row * 128 + ((ch ^ (row & 7)) * 16);
                const void* g = bases[arr] + (size_t)(rb[arr] + row) * EMB + k0 + ch * 8;
                CP_ASYNC16(soff, g);
            }
        }
        CP_COMMIT();
    };

    auto compute_stage = [&](int s) {
        const uint32_t sah = smb + s * STAGE_BYTES + 0 * TILE_BYTES;
        const uint32_t sal = smb + s * STAGE_BYTES + 1 * TILE_BYTES;
        const uint32_t sbh = smb + s * STAGE_BYTES + 2 * TILE_BYTES;
        const uint32_t sbl = smb + s * STAGE_BYTES + 3 * TILE_BYTES;
#pragma unroll
        for (int ks = 0; ks < 4; ks++) {
            uint32_t ahi[4][4], alo[4][4];
#pragma unroll
            for (int mi = 0; mi < 4; mi++) {
                int row = wm * 64 + mi * 16 + (lane & 15);
                int ch = ks * 2 + (lane >> 4);
                uint32_t off = row * 128 + ((ch ^ (row & 7)) * 16);
                LDSM_X4(ahi[mi], sah + off);
                LDSM_X4(alo[mi], sal + off);
            }
            uint32_t bhi[4][2], blo[4][2];
#pragma unroll
            for (int ni = 0; ni < 4; ni++) {
                int row = wn * 32 + ni * 8 + (lane & 7);
                int ch = ks * 2 + ((lane >> 3) & 1);
                uint32_t off = row * 128 + ((ch ^ (row & 7)) * 16);
                LDSM_X2(bhi[ni], sbh + off);
                LDSM_X2(blo[ni], sbl + off);
            }
#pragma unroll
            for (int mi = 0; mi < 4; mi++)
#pragma unroll
                for (int ni = 0; ni < 4; ni++) {
                    MMA16816(acc[mi][ni], ahi[mi], bhi[ni]);
                    MMA16816(acc[mi][ni], ahi[mi], blo[ni]);
                    MMA16816(acc[mi][ni], alo[mi], bhi[ni]);
                }
        }
    };

    load_stage(0, 0);
    load_stage(1, 1);

    for (int t = 0; t < NKTILE; t++) {
        if (t < NKTILE - 2) CP_WAIT1(); else CP_WAIT0();
        __syncthreads();
        compute_stage(t & 1);
        __syncthreads();
        if (t + 2 < NKTILE) load_stage(t & 1, t + 2);
    }

#pragma unroll
    for (int mi = 0; mi < 4; mi++) {
#pragma unroll
        for (int ni = 0; ni < 4; ni++) {
            int row = rowBase + wm * 64 + mi * 16 + (lane >> 2);
            int col = colBase + wn * 32 + ni * 8 + (lane & 3) * 2;
            if (SPLIT) {
                *(uint32_t*)&Chi[(size_t)row * EMB + col] =
                    pack_hi2(acc[mi][ni][0], acc[mi][ni][1]);
                *(uint32_t*)&Clo[(size_t)row * EMB + col] =
                    pack_lo2(acc[mi][ni][0], acc[mi][ni][1]);
                *(uint32_t*)&Chi[(size_t)(row + 8) * EMB + col] =
                    pack_hi2(acc[mi][ni][2], acc[mi][ni][3]);
                *(uint32_t*)&Clo[(size_t)(row + 8) * EMB + col] =
                    pack_lo2(acc[mi][ni][2], acc[mi][ni][3]);
            } else {
                *(float2*)&C[(size_t)row * EMB + col] =
                    make_float2(acc[mi][ni][0], acc[mi][ni][1]);
                *(float2*)&C[(size_t)(row + 8) * EMB + col] =
                    make_float2(acc[mi][ni][2], acc[mi][ni][3]);
            }
        }
    }
}

// ======================= Flash attention on mma.sync (split-bf16) =======================
// CTA: 128 q rows for one (b,h). 8 warps x 16 q rows. K-tiles of 64 keys.
// SMEM: Qhi/Qlo [128x64] + double-buffered {Khi,Klo,Vhi,Vlo} [64x64] tiles.
#define ATILE (128 * 128)          // 16KB
#define KVTILE (64 * 128)          // 8KB
#define KVSTAGE (4 * KVTILE)       // 32KB
#define Q_OFF 0
#define KV_OFF (2 * ATILE)         // 32KB
#define ATTN_SMEM (2 * ATILE + 2 * KVSTAGE)  // 96KB

__global__ void __launch_bounds__(256, 1)
attn_mma_kernel(const __nv_bfloat16* __restrict__ Qhi, const __nv_bfloat16* __restrict__ Qlo,
                const __nv_bfloat16* __restrict__ Khi, const __nv_bfloat16* __restrict__ Klo,
                const __nv_bfloat16* __restrict__ Vhi, const __nv_bfloat16* __restrict__ Vlo,
                __nv_bfloat16* __restrict__ Ohi, __nv_bfloat16* __restrict__ Olo) {
    extern __shared__ char sm[];
    const uint32_t smb = smem_u32(sm);

    const int tid = threadIdx.x;
    const int lane = tid & 31;
    const int wid = tid >> 5;
    const int qt = gridDim.x - 1 - blockIdx.x;   // big tiles first
    const int h  = blockIdx.y;
    const int b  = blockIdx.z;

    const size_t base = (size_t)b * SEQ * EMB + (size_t)h * HDIM;
    const __nv_bfloat16* qh = Qhi + base;
    const __nv_bfloat16* ql = Qlo + base;
    const __nv_bfloat16* kh = Khi + base;
    const __nv_bfloat16* kl = Klo + base;
    const __nv_bfloat16* vh = Vhi + base;
    const __nv_bfloat16* vl = Vlo + base;

    auto load_kv = [&](int s, int kt) {
        const __nv_bfloat16* bases[4] = {kh, kl, vh, vl};
#pragma unroll
        for (int it = 0; it < 8; it++) {
            int idx = tid + it * 256;      // 0..2047
            int arr = idx >> 9;            // 0..3
            int rc  = idx & 511;
            int row = rc >> 3;
            int ch  = rc & 7;
            uint32_t soff = smb + KV_OFF + s * KVSTAGE + arr * KVTILE
                          + row * 128 + ((ch ^ (row & 7)) * 16);
            CP_ASYNC16(soff, bases[arr] + (size_t)(kt * 64 + row) * EMB + ch * 8);
        }
        CP_COMMIT();
    };

    // group 0: Q tile (128 rows x 64 hd, hi+lo), swizzled
#pragma unroll
    for (int it = 0; it < 8; it++) {
        int idx = tid + it * 256;          // 0..2047
        int arr = idx >> 10;               // 0: hi, 1: lo
        int rc  = idx & 1023;
        int row = rc >> 3;
        int ch  = rc & 7;
        uint32_t soff = smb + Q_OFF + arr * ATILE + row * 128 + ((ch ^ (row & 7)) * 16);
        const __nv_bfloat16* src = (arr == 0) ? qh : ql;
        CP_ASYNC16(soff, src + (size_t)(qt * 128 + row) * EMB + ch * 8);
    }
    CP_COMMIT();

    const int ktmax = 2 * qt + 1;
    load_kv(0, 0);   // group 1: KV stage 0

    float o[8][4];
#pragma unroll
    for (int j = 0; j < 8; j++)
#pragma unroll
        for (int c = 0; c < 4; c++) o[j][c] = 0.f;
    float m0 = -1e30f, m1 = -1e30f, l0 = 0.f, l1 = 0.f;

    const float sscale = 0.125f;
    const int qrow0 = qt * 128 + wid * 16 + (lane >> 2);  // row of c0/c1
    const uint32_t sqh = smb + Q_OFF;
    const uint32_t sql = smb + Q_OFF + ATILE;

    for (int kt = 0; kt <= ktmax; kt++) {
        if (kt < ktmax) { load_kv((kt + 1) & 1, kt + 1); CP_WAIT1(); }
        else           { CP_WAIT0(); }
        __syncthreads();

        // warp fully above diagonal? -> skip math (uniform per warp)
        bool active = (kt * 64 <= qt * 128 + wid * 16 + 15);
        if (active) {
            const int s = kt & 1;
            const uint32_t skh = smb + KV_OFF + s * KVSTAGE + 0 * KVTILE;
            const uint32_t skl = smb + KV_OFF + s * KVSTAGE + 1 * KVTILE;
            const uint32_t svh = smb + KV_OFF + s * KVSTAGE + 2 * KVTILE;
            const uint32_t svl = smb + KV_OFF + s * KVSTAGE + 3 * KVTILE;

            // ---- S = Q K^T (3-split) ----
            float sc[8][4];
#pragma unroll
            for (int j = 0; j < 8; j++)
#pragma unroll
                for (int c = 0; c < 4; c++) sc[j][c] = 0.f;

#pragma unroll
            for (int ks = 0; ks < 4; ks++) {
                uint32_t ah[4], al[4];
                {
                    int row = wid * 16 + (lane & 15);
                    int ch = ks * 2 + (lane >> 4);
                    uint32_t off = row * 128 + ((ch ^ (row & 7)) * 16);
                    LDSM_X4(ah, sqh + off);
                    LDSM_X4(al, sql + off);
                }
#pragma unroll
                for (int j = 0; j < 8; j++) {
                    uint32_t bh[2], bl[2];
                    int row = j * 8 + (lane & 7);
                    int ch = ks * 2 + ((lane >> 3) & 1);
                    uint32_t off = row * 128 + ((ch ^ (row & 7)) * 16);
                    LDSM_X2(bh, skh + off);
                    LDSM_X2(bl, skl + off);
                    MMA16816(sc[j], ah, bh);
                    MMA16816(sc[j], ah, bl);
                    MMA16816(sc[j], al, bh);
                }
            }

            // ---- scale + causal mask ----
            bool diag = (kt * 64 + 63 > qt * 128 + wid * 16);
#pragma unroll
            for (int j = 0; j < 8; j++) {
                int col = kt * 64 + j * 8 + (lane & 3) * 2;
#pragma unroll
                for (int c = 0; c < 4; c++) {
                    float v = sc[j][c] * sscale;
                    if (diag) {
                        int cc = col + (c & 1);
                        int rr = qrow0 + ((c >= 2) ? 8 : 0);
                        if (cc > rr) v = -1e30f;
                    }
                    sc[j][c] = v;
                }
            }

            // ---- online softmax (rows split c01 / c23) ----
            float mt0 = -1e30f, mt1 = -1e30f;
#pragma unroll
            for (int j = 0; j < 8; j++) {
                mt0 = fmaxf(mt0, fmaxf(sc[j][0], sc[j][1]));
                mt1 = fmaxf(mt1, fmaxf(sc[j][2], sc[j][3]));
            }
            mt0 = fmaxf(mt0, __shfl_xor_sync(0xffffffffu, mt0, 1));
            mt0 = fmaxf(mt0, __shfl_xor_sync(0xffffffffu, mt0, 2));
            mt1 = fmaxf(mt1, __shfl_xor_sync(0xffffffffu, mt1, 1));
            mt1 = fmaxf(mt1, __shfl_xor_sync(0xffffffffu, mt1, 2));

            float mn0 = fmaxf(m0, mt0), mn1 = fmaxf(m1, mt1);
            float corr0 = __expf(m0 - mn0), corr1 = __expf(m1 - mn1);

            float ps0 = 0.f, ps1 = 0.f;
#pragma unroll
            for (int j = 0; j < 8; j++) {
                float p0 = __expf(sc[j][0] - mn0);
                float p1 = __expf(sc[j][1] - mn0);
                float p2 = __expf(sc[j][2] - mn1);
                float p3 = __expf(sc[j][3] - mn1);
                sc[j][0] = p0; sc[j][1] = p1; sc[j][2] = p2; sc[j][3] = p3;
                ps0 += p0 + p1; ps1 += p2 + p3;
            }
            ps0 += __shfl_xor_sync(0xffffffffu, ps0, 1);
            ps0 += __shfl_xor_sync(0xffffffffu, ps0, 2);
            ps1 += __shfl_xor_sync(0xffffffffu, ps1, 1);
            ps1 += __shfl_xor_sync(0xffffffffu, ps1, 2);

            l0 = l0 * corr0 + ps0; m0 = mn0;
            l1 = l1 * corr1 + ps1; m1 = mn1;
#pragma unroll
            for (int j = 0; j < 8; j++) {
                o[j][0] *= corr0; o[j][1] *= corr0;
                o[j][2] *= corr1; o[j][3] *= corr1;
            }

            // ---- O += P V (3-split) ----
#pragma unroll
            for (int ks = 0; ks < 4; ks++) {
                uint32_t ph[4], pl[4];
                ph[0] = pack_hi2(sc[2*ks][0],   sc[2*ks][1]);
                ph[1] = pack_hi2(sc[2*ks][2],   sc[2*ks][3]);
                ph[2] = pack_hi2(sc[2*ks+1][0], sc[2*ks+1][1]);
                ph[3] = pack_hi2(sc[2*ks+1][2], sc[2*ks+1][3]);
                pl[0] = pack_lo2(sc[2*ks][0],   sc[2*ks][1]);
                pl[1] = pack_lo2(sc[2*ks][2],   sc[2*ks][3]);
                pl[2] = pack_lo2(sc[2*ks+1][0], sc[2*ks+1][1]);
                pl[3] = pack_lo2(sc[2*ks+1][2], sc[2*ks+1][3]);
#pragma unroll
                for (int j = 0; j < 4; j++) {
                    uint32_t bh[4], bl[4];
                    int row = ks * 16 + (lane & 15);
                    int ch = j * 2 + (lane >> 4);
                    uint32_t off = row * 128 + ((ch ^ (row & 7)) * 16);
                    LDSM_X4T(bh, svh + off);
                    LDSM_X4T(bl, svl + off);
                    MMA16816(o[2*j],     ph, (&bh[0]));
                    MMA16816(o[2*j],     ph, (&bl[0]));
                    MMA16816(o[2*j],     pl, (&bh[0]));
                    MMA16816(o[2*j + 1], ph, (&bh[2]));
                    MMA16816(o[2*j + 1], ph, (&bl[2]));
                    MMA16816(o[2*j + 1], pl, (&bh[2]));
                }
            }
        }
        __syncthreads();
    }

    // ---- normalize + split-store ----
    float inv0 = 1.f / l0, inv1 = 1.f / l1;
    const int row0 = b * SEQ + qt * 128 + wid * 16 + (lane >> 2);
#pragma unroll
    for (int j = 0; j < 8; j++) {
        float a0 = o[j][0] * inv0, a1 = o[j][1] * inv0;
        float a2 = o[j][2] * inv1, a3 = o[j][3] * inv1;
        size_t off0 = (size_t)row0 * EMB + h * HDIM + j * 8 + (lane & 3) * 2;
        size_t off1 = off0 + (size_t)8 * EMB;
        *(uint32_t*)&Ohi[off0] = pack_hi2(a0, a1);
        *(uint32_t*)&Olo[off0] = pack_lo2(a0, a1);
        *(uint32_t*)&Ohi[off1] = pack_hi2(a2, a3);
        *(uint32_t*)&Olo[off1] = pack_lo2(a2, a3);
    }
}

// ======================= Scratch =======================
__device__ __nv_bfloat16 g_xhi[TOK * EMB], g_xlo[TOK * EMB];
__device__ __nv_bfloat16 g_qhi[TOK * EMB], g_qlo[TOK * EMB];
__device__ __nv_bfloat16 g_khi[TOK * EMB], g_klo[TOK * EMB];
__device__ __nv_bfloat16 g_vhi[TOK * EMB], g_vlo[TOK * EMB];
__device__ __nv_bfloat16 g_ahi[TOK * EMB], g_alo[TOK * EMB];
__device__ __nv_bfloat16 g_wqhi[EMB * EMB], g_wqlo[EMB * EMB];
__device__ __nv_bfloat16 g_wkhi[EMB * EMB], g_wklo[EMB * EMB];
__device__ __nv_bfloat16 g_wvhi[EMB * EMB], g_wvlo[EMB * EMB];
__device__ __nv_bfloat16 g_wohi[EMB * EMB], g_wolo[EMB * EMB];

extern "C" void kernel_launch(void* const* d_in, const int* in_sizes, int n_in,
                              void* d_out, int out_size) {
    const float* x  = (const float*)d_in[0];
    const float* Wq = (const float*)d_in[2];
    const float* Wk = (const float*)d_in[3];
    const float* Wv = (const float*)d_in[4];
    const float* Wo = (const float*)d_in[5];
    float* out = (float*)d_out;

    __nv_bfloat16 *xhi, *xlo, *qhi, *qlo, *khi, *klo, *vhi, *vlo, *ahi, *alo;
    __nv_bfloat16 *wqhi, *wqlo, *wkhi, *wklo, *wvhi, *wvlo, *wohi, *wolo;
    cudaGetSymbolAddress((void**)&xhi, g_xhi);   cudaGetSymbolAddress((void**)&xlo, g_xlo);
    cudaGetSymbolAddress((void**)&qhi, g_qhi);   cudaGetSymbolAddress((void**)&qlo, g_qlo);
    cudaGetSymbolAddress((void**)&khi, g_khi);   cudaGetSymbolAddress((void**)&klo, g_klo);
    cudaGetSymbolAddress((void**)&vhi, g_vhi);   cudaGetSymbolAddress((void**)&vlo, g_vlo);
    cudaGetSymbolAddress((void**)&ahi, g_ahi);   cudaGetSymbolAddress((void**)&alo, g_alo);
    cudaGetSymbolAddress((void**)&wqhi, g_wqhi); cudaGetSymbolAddress((void**)&wqlo, g_wqlo);
    cudaGetSymbolAddress((void**)&wkhi, g_wkhi); cudaGetSymbolAddress((void**)&wklo, g_wklo);
    cudaGetSymbolAddress((void**)&wvhi, g_wvhi); cudaGetSymbolAddress((void**)&wvlo, g_wvlo);
    cudaGetSymbolAddress((void**)&wohi, g_wohi); cudaGetSymbolAddress((void**)&wolo, g_wolo);

    static bool attrs_set = false;
    if (!attrs_set) {
        cudaFuncSetAttribute(gemm_mma_kernel<true>,
                             cudaFuncAttributeMaxDynamicSharedMemorySize, GEMM_SMEM);
        cudaFuncSetAttribute(gemm_mma_kernel<false>,
                             cudaFuncAttributeMaxDynamicSharedMemorySize, GEMM_SMEM);
        cudaFuncSetAttribute(attn_mma_kernel,
                             cudaFuncAttributeMaxDynamicSharedMemorySize, ATTN_SMEM);
        attrs_set = true;
    }

    const int XN4 = TOK * EMB / 4;
    const int WN4 = EMB * EMB / 4;

    cvt_split_kernel<<<(XN4 + 255) / 256, 256>>>(x, xhi, xlo, XN4);
    cvt_split_kernel<<<(WN4 + 255) / 256, 256>>>(Wq, wqhi, wqlo, WN4);
    cvt_split_kernel<<<(WN4 + 255) / 256, 256>>>(Wk, wkhi, wklo, WN4);
    cvt_split_kernel<<<(WN4 + 255) / 256, 256>>>(Wv, wvhi, wvlo, WN4);
    cvt_split_kernel<<<(WN4 + 255) / 256, 256>>>(Wo, wohi, wolo, WN4);

    dim3 gemmGrid(EMB / NT, TOK / MT);   // (8, 32)
    gemm_mma_kernel<true><<<gemmGrid, 256, GEMM_SMEM>>>(xhi, xlo, wqhi, wqlo,
                                                        nullptr, qhi, qlo);
    gemm_mma_kernel<true><<<gemmGrid, 256, GEMM_SMEM>>>(xhi, xlo, wkhi, wklo,
                                                        nullptr, khi, klo);
    gemm_mma_kernel<true><<<gemmGrid, 256, GEMM_SMEM>>>(xhi, xlo, wvhi, wvlo,
                                                        nullptr, vhi, vlo);

    dim3 attnGrid(SEQ / 128, HEADS, BATCH);   // (16, 16, 2)
    attn_mma_kernel<<<attnGrid, 256, ATTN_SMEM>>>(qhi, qlo, khi, klo, vhi, vlo, ahi, alo);

    gemm_mma_kernel<false><<<gemmGrid, 256, GEMM_SMEM>>>(ahi, alo, wohi, wolo,
                                                         out, nullptr, nullptr);
}

// round 7
// speedup vs baseline: 11.9948x; 1.0368x over previous
#include <cuda_runtime.h>
#include <cuda_bf16.h>
#include <cstdint>
#include <math.h>

#define BATCH 2
#define SEQ   2048
#define EMB   1024
#define HEADS 16
#define HDIM  64
#define TOK   (BATCH * SEQ)   // 4096

// ======================= PTX helpers (sm_80-era ISA only) =======================
__device__ __forceinline__ uint32_t smem_u32(const void* p) {
    uint32_t a;
    asm("{ .reg .u64 t; cvta.to.shared.u64 t, %1; cvt.u32.u64 %0, t; }"
        : "=r"(a) : "l"(p));
    return a;
}

#define LDSM_X4(r, a) \
    asm volatile("ldmatrix.sync.aligned.m8n8.x4.shared.b16 {%0,%1,%2,%3}, [%4];" \
                 : "=r"((r)[0]), "=r"((r)[1]), "=r"((r)[2]), "=r"((r)[3]) : "r"(a))

#define LDSM_X4T(r, a) \
    asm volatile("ldmatrix.sync.aligned.m8n8.x4.trans.shared.b16 {%0,%1,%2,%3}, [%4];" \
                 : "=r"((r)[0]), "=r"((r)[1]), "=r"((r)[2]), "=r"((r)[3]) : "r"(a))

#define MMA16816(d, a, b) \
    asm volatile("mma.sync.aligned.m16n8k16.row.col.f32.bf16.bf16.f32 " \
                 "{%0,%1,%2,%3}, {%4,%5,%6,%7}, {%8,%9}, {%0,%1,%2,%3};" \
                 : "+f"((d)[0]), "+f"((d)[1]), "+f"((d)[2]), "+f"((d)[3]) \
                 : "r"((a)[0]), "r"((a)[1]), "r"((a)[2]), "r"((a)[3]), \
                   "r"((b)[0]), "r"((b)[1]))

#define CP_ASYNC16(saddr, gaddr) \
    asm volatile("cp.async.cg.shared.global [%0], [%1], 16;" :: "r"(saddr), "l"(gaddr))
#define CP_COMMIT() asm volatile("cp.async.commit_group;" ::: "memory")
#define CP_WAIT1() asm volatile("cp.async.wait_group 1;" ::: "memory")
#define CP_WAIT0() asm volatile("cp.async.wait_group 0;" ::: "memory")

__device__ __forceinline__ uint32_t pack_hi2(float x, float y) {
    __nv_bfloat162 t = __halves2bfloat162(__float2bfloat16(x), __float2bfloat16(y));
    return *(uint32_t*)&t;
}
__device__ __forceinline__ uint32_t pack_lo2(float x, float y) {
    __nv_bfloat16 hx = __float2bfloat16(x), hy = __float2bfloat16(y);
    __nv_bfloat162 t = __halves2bfloat162(__float2bfloat16(x - __bfloat162float(hx)),
                                          __float2bfloat16(y - __bfloat162float(hy)));
    return *(uint32_t*)&t;
}

// ======================= fused fp32 -> (bf16 hi, lo) split: x + 4 weights =======================
__global__ void cvt_all_kernel(const float* __restrict__ x,
                               const float* __restrict__ w0, const float* __restrict__ w1,
                               const float* __restrict__ w2, const float* __restrict__ w3,
                               __nv_bfloat16* __restrict__ xhi, __nv_bfloat16* __restrict__ xlo,
                               __nv_bfloat16* __restrict__ h0, __nv_bfloat16* __restrict__ l0,
                               __nv_bfloat16* __restrict__ h1, __nv_bfloat16* __restrict__ l1,
                               __nv_bfloat16* __restrict__ h2, __nv_bfloat16* __restrict__ l2,
                               __nv_bfloat16* __restrict__ h3, __nv_bfloat16* __restrict__ l3) {
    const int z = blockIdx.y;
    const float* in;
    __nv_bfloat16 *hi, *lo;
    int n4;
    switch (z) {
        case 0: in = x;  hi = xhi; lo = xlo; n4 = TOK * EMB / 4; break;
        case 1: in = w0; hi = h0;  lo = l0;  n4 = EMB * EMB / 4; break;
        case 2: in = w1; hi = h1;  lo = l1;  n4 = EMB * EMB / 4; break;
        case 3: in = w2; hi = h2;  lo = l2;  n4 = EMB * EMB / 4; break;
        default: in = w3; hi = h3; lo = l3;  n4 = EMB * EMB / 4; break;
    }
    int i = blockIdx.x * blockDim.x + threadIdx.x;
    if (i >= n4) return;
    float4 v = *(const float4*)(in + i * 4);
    *(uint32_t*)(hi + i * 4)     = pack_hi2(v.x, v.y);
    *(uint32_t*)(hi + i * 4 + 2) = pack_hi2(v.z, v.w);
    *(uint32_t*)(lo + i * 4)     = pack_lo2(v.x, v.y);
    *(uint32_t*)(lo + i * 4 + 2) = pack_lo2(v.z, v.w);
}

// ======================= mma.sync split-bf16 GEMM (3-stage ring) =======================
#define MT 128
#define NT 128
#define KT 64
#define NKTILE (EMB / KT)            // 16
#define TILE_BYTES (128 * KT * 2)    // 16KB
#define STAGE_BYTES (4 * TILE_BYTES) // 64KB
#define GEMM_SMEM (3 * STAGE_BYTES)  // 192KB

template <bool SPLIT>
__device__ __forceinline__ void gemm_core(
        const __nv_bfloat16* __restrict__ Ahi, const __nv_bfloat16* __restrict__ Alo,
        const __nv_bfloat16* __restrict__ Bhi, const __nv_bfloat16* __restrict__ Blo,
        float* __restrict__ C, __nv_bfloat16* __restrict__ Chi, __nv_bfloat16* __restrict__ Clo,
        const uint32_t smb, int rowBase, int colBase) {
    const int tid = threadIdx.x;
    const int lane = tid & 31;
    const int wid = tid >> 5;
    const int wm = wid >> 2;
    const int wn = wid & 3;

    float acc[4][4][4];
#pragma unroll
    for (int mi = 0; mi < 4; mi++)
#pragma unroll
        for (int ni = 0; ni < 4; ni++)
#pragma unroll
            for (int j = 0; j < 4; j++) acc[mi][ni][j] = 0.f;

    auto load_stage = [&](int s, int kt) {
        const int k0 = kt * KT;
        const __nv_bfloat16* bases[4] = {Ahi, Alo, Bhi, Blo};
        const int rb[4] = {rowBase, rowBase, colBase, colBase};
#pragma unroll
        for (int arr = 0; arr < 4; arr++) {
            uint32_t sb = smb + s * STAGE_BYTES + arr * TILE_BYTES;
#pragma unroll
            for (int it = 0; it < 4; it++) {
                int idx = tid + it * 256;
                int row = idx >> 3;
                int ch  = idx & 7;
                uint32_t soff = sb + row * 128 + ((ch ^ (row & 7)) * 16);
                const void* g = bases[arr] + (size_t)(rb[arr] + row) * EMB + k0 + ch * 8;
                CP_ASYNC16(soff, g);
            }
        }
        CP_COMMIT();
    };

    auto compute_stage = [&](int s) {
        const uint32_t sah = smb + s * STAGE_BYTES + 0 * TILE_BYTES;
        const uint32_t sal = smb + s * STAGE_BYTES + 1 * TILE_BYTES;
        const uint32_t sbh = smb + s * STAGE_BYTES + 2 * TILE_BYTES;
        const uint32_t sbl = smb + s * STAGE_BYTES + 3 * TILE_BYTES;
#pragma unroll
        for (int ks = 0; ks < 4; ks++) {
            uint32_t ahi[4][4], alo[4][4];
#pragma unroll
            for (int mi = 0; mi < 4; mi++) {
                int row = wm * 64 + mi * 16 + (lane & 15);
                int ch = ks * 2 + (lane >> 4);
                uint32_t off = row * 128 + ((ch ^ (row & 7)) * 16);
                LDSM_X4(ahi[mi], sah + off);
                LDSM_X4(alo[mi], sal + off);
            }
            // B frags: x4 loads cover two ni tiles at once
            uint32_t bhi[4][2], blo[4][2];
#pragma unroll
            for (int nip = 0; nip < 2; nip++) {
                int ni = nip * 2;
                int row = wn * 32 + (ni + (lane >> 4)) * 8 + (lane & 7);
                int ch = ks * 2 + ((lane >> 3) & 1);
                uint32_t off = row * 128 + ((ch ^ (row & 7)) * 16);
                uint32_t t4[4];
                LDSM_X4(t4, sbh + off);
                bhi[ni][0] = t4[0]; bhi[ni][1] = t4[1];
                bhi[ni + 1][0] = t4[2]; bhi[ni + 1][1] = t4[3];
                LDSM_X4(t4, sbl + off);
                blo[ni][0] = t4[0]; blo[ni][1] = t4[1];
                blo[ni + 1][0] = t4[2]; blo[ni + 1][1] = t4[3];
            }
#pragma unroll
            for (int mi = 0; mi < 4; mi++)
#pragma unroll
                for (int ni = 0; ni < 4; ni++) {
                    MMA16816(acc[mi][ni], ahi[mi], bhi[ni]);
                    MMA16816(acc[mi][ni], ahi[mi], blo[ni]);
                    MMA16816(acc[mi][ni], alo[mi], bhi[ni]);
                }
        }
    };

    // 3-stage ring, single sync per iteration
    load_stage(0, 0);
    load_stage(1, 1);
    for (int t = 0; t < NKTILE; t++) {
        if (t < NKTILE - 1) CP_WAIT1(); else CP_WAIT0();
        __syncthreads();
        if (t + 2 < NKTILE) load_stage((t + 2) % 3, t + 2);
        compute_stage(t % 3);
    }

#pragma unroll
    for (int mi = 0; mi < 4; mi++) {
#pragma unroll
        for (int ni = 0; ni < 4; ni++) {
            int row = rowBase + wm * 64 + mi * 16 + (lane >> 2);
            int col = colBase + wn * 32 + ni * 8 + (lane & 3) * 2;
            if (SPLIT) {
                *(uint32_t*)&Chi[(size_t)row * EMB + col] =
                    pack_hi2(acc[mi][ni][0], acc[mi][ni][1]);
                *(uint32_t*)&Clo[(size_t)row * EMB + col] =
                    pack_lo2(acc[mi][ni][0], acc[mi][ni][1]);
                *(uint32_t*)&Chi[(size_t)(row + 8) * EMB + col] =
                    pack_hi2(acc[mi][ni][2], acc[mi][ni][3]);
                *(uint32_t*)&Clo[(size_t)(row + 8) * EMB + col] =
                    pack_lo2(acc[mi][ni][2], acc[mi][ni][3]);
            } else {
                *(float2*)&C[(size_t)row * EMB + col] =
                    make_float2(acc[mi][ni][0], acc[mi][ni][1]);
                *(float2*)&C[(size_t)(row + 8) * EMB + col] =
                    make_float2(acc[mi][ni][2], acc[mi][ni][3]);
            }
        }
    }
}

// Fused QKV: blockIdx.z selects weight/output set.
__global__ void __launch_bounds__(256, 1)
gemm_qkv_kernel(const __nv_bfloat16* __restrict__ xhi, const __nv_bfloat16* __restrict__ xlo,
                const __nv_bfloat16* __restrict__ wqh, const __nv_bfloat16* __restrict__ wql,
                const __nv_bfloat16* __restrict__ wkh, const __nv_bfloat16* __restrict__ wkl,
                const __nv_bfloat16* __restrict__ wvh, const __nv_bfloat16* __restrict__ wvl,
                __nv_bfloat16* __restrict__ qh, __nv_bfloat16* __restrict__ ql,
                __nv_bfloat16* __restrict__ kh, __nv_bfloat16* __restrict__ kl,
                __nv_bfloat16* __restrict__ vh, __nv_bfloat16* __restrict__ vl) {
    extern __shared__ char sm[];
    const int z = blockIdx.z;
    const __nv_bfloat16* Bh = (z == 0) ? wqh : (z == 1) ? wkh : wvh;
    const __nv_bfloat16* Bl = (z == 0) ? wql : (z == 1) ? wkl : wvl;
    __nv_bfloat16* Ch = (z == 0) ? qh : (z == 1) ? kh : vh;
    __nv_bfloat16* Cl = (z == 0) ? ql : (z == 1) ? kl : vl;
    gemm_core<true>(xhi, xlo, Bh, Bl, nullptr, Ch, Cl, smem_u32(sm),
                    blockIdx.y * MT, blockIdx.x * NT);
}

__global__ void __launch_bounds__(256, 1)
gemm_o_kernel(const __nv_bfloat16* __restrict__ ahi, const __nv_bfloat16* __restrict__ alo,
              const __nv_bfloat16* __restrict__ woh, const __nv_bfloat16* __restrict__ wol,
              float* __restrict__ out) {
    extern __shared__ char sm[];
    gemm_core<false>(ahi, alo, woh, wol, out, nullptr, nullptr, smem_u32(sm),
                     blockIdx.y * MT, blockIdx.x * NT);
}

// ======================= Flash attention on mma.sync (split-bf16) =======================
#define ATILE (128 * 128)          // 16KB
#define KVTILE (64 * 128)          // 8KB
#define KVSTAGE (4 * KVTILE)       // 32KB
#define Q_OFF 0
#define KV_OFF (2 * ATILE)         // 32KB
#define ATTN_SMEM (2 * ATILE + 2 * KVSTAGE)  // 96KB

__global__ void __launch_bounds__(256, 1)
attn_mma_kernel(const __nv_bfloat16* __restrict__ Qhi, const __nv_bfloat16* __restrict__ Qlo,
                const __nv_bfloat16* __restrict__ Khi, const __nv_bfloat16* __restrict__ Klo,
                const __nv_bfloat16* __restrict__ Vhi, const __nv_bfloat16* __restrict__ Vlo,
                __nv_bfloat16* __restrict__ Ohi, __nv_bfloat16* __restrict__ Olo) {
    extern __shared__ char sm[];
    const uint32_t smb = smem_u32(sm);

    const int tid = threadIdx.x;
    const int lane = tid & 31;
    const int wid = tid >> 5;
    const int qt = gridDim.x - 1 - blockIdx.x;   // big tiles first
    const int h  = blockIdx.y;
    const int b  = blockIdx.z;

    const size_t base = (size_t)b * SEQ * EMB + (size_t)h * HDIM;
    const __nv_bfloat16* qh = Qhi + base;
    const __nv_bfloat16* ql = Qlo + base;
    const __nv_bfloat16* kh = Khi + base;
    const __nv_bfloat16* kl = Klo + base;
    const __nv_bfloat16* vh = Vhi + base;
    const __nv_bfloat16* vl = Vlo + base;

    auto load_kv = [&](int s, int kt) {
        const __nv_bfloat16* bases[4] = {kh, kl, vh, vl};
#pragma unroll
        for (int it = 0; it < 8; it++) {
            int idx = tid + it * 256;
            int arr = idx >> 9;
            int rc  = idx & 511;
            int row = rc >> 3;
            int ch  = rc & 7;
            uint32_t soff = smb + KV_OFF + s * KVSTAGE + arr * KVTILE
                          + row * 128 + ((ch ^ (row & 7)) * 16);
            CP_ASYNC16(soff, bases[arr] + (size_t)(kt * 64 + row) * EMB + ch * 8);
        }
        CP_COMMIT();
    };

    // group 0: Q tile
#pragma unroll
    for (int it = 0; it < 8; it++) {
        int idx = tid + it * 256;
        int arr = idx >> 10;
        int rc  = idx & 1023;
        int row = rc >> 3;
        int ch  = rc & 7;
        uint32_t soff = smb + Q_OFF + arr * ATILE + row * 128 + ((ch ^ (row & 7)) * 16);
        const __nv_bfloat16* src = (arr == 0) ? qh : ql;
        CP_ASYNC16(soff, src + (size_t)(qt * 128 + row) * EMB + ch * 8);
    }
    CP_COMMIT();

    const int ktmax = 2 * qt + 1;
    load_kv(0, 0);

    float o[8][4];
#pragma unroll
    for (int j = 0; j < 8; j++)
#pragma unroll
        for (int c = 0; c < 4; c++) o[j][c] = 0.f;
    float m0 = -1e30f, m1 = -1e30f, l0 = 0.f, l1 = 0.f;

    const float sscale = 0.125f;
    const int qrow0 = qt * 128 + wid * 16 + (lane >> 2);
    const uint32_t sqh = smb + Q_OFF;
    const uint32_t sql = smb + Q_OFF + ATILE;

    for (int kt = 0; kt <= ktmax; kt++) {
        if (kt < ktmax) { load_kv((kt + 1) & 1, kt + 1); CP_WAIT1(); }
        else           { CP_WAIT0(); }
        __syncthreads();

        bool active = (kt * 64 <= qt * 128 + wid * 16 + 15);
        if (active) {
            const int s = kt & 1;
            const uint32_t skh = smb + KV_OFF + s * KVSTAGE + 0 * KVTILE;
            const uint32_t skl = smb + KV_OFF + s * KVSTAGE + 1 * KVTILE;
            const uint32_t svh = smb + KV_OFF + s * KVSTAGE + 2 * KVTILE;
            const uint32_t svl = smb + KV_OFF + s * KVSTAGE + 3 * KVTILE;

            // ---- S = Q K^T (3-split), K frags via x4 pair loads ----
            float sc[8][4];
#pragma unroll
            for (int j = 0; j < 8; j++)
#pragma unroll
                for (int c = 0; c < 4; c++) sc[j][c] = 0.f;

#pragma unroll
            for (int ks = 0; ks < 4; ks++) {
                uint32_t ah[4], al[4];
                {
                    int row = wid * 16 + (lane & 15);
                    int ch = ks * 2 + (lane >> 4);
                    uint32_t off = row * 128 + ((ch ^ (row & 7)) * 16);
                    LDSM_X4(ah, sqh + off);
                    LDSM_X4(al, sql + off);
                }
#pragma unroll
                for (int jp = 0; jp < 4; jp++) {
                    int j = jp * 2;
                    int row = (j + (lane >> 4)) * 8 + (lane & 7);
                    int ch = ks * 2 + ((lane >> 3) & 1);
                    uint32_t off = row * 128 + ((ch ^ (row & 7)) * 16);
                    uint32_t bh[4], bl[4];
                    LDSM_X4(bh, skh + off);
                    LDSM_X4(bl, skl + off);
                    MMA16816(sc[j],     ah, (&bh[0]));
                    MMA16816(sc[j],     ah, (&bl[0]));
                    MMA16816(sc[j],     al, (&bh[0]));
                    MMA16816(sc[j + 1], ah, (&bh[2]));
                    MMA16816(sc[j + 1], ah, (&bl[2]));
                    MMA16816(sc[j + 1], al, (&bh[2]));
                }
            }

            // ---- scale + causal mask ----
            bool diag = (kt * 64 + 63 > qt * 128 + wid * 16);
#pragma unroll
            for (int j = 0; j < 8; j++) {
                int col = kt * 64 + j * 8 + (lane & 3) * 2;
#pragma unroll
                for (int c = 0; c < 4; c++) {
                    float v = sc[j][c] * sscale;
                    if (diag) {
                        int cc = col + (c & 1);
                        int rr = qrow0 + ((c >= 2) ? 8 : 0);
                        if (cc > rr) v = -1e30f;
                    }
                    sc[j][c] = v;
                }
            }

            // ---- online softmax ----
            float mt0 = -1e30f, mt1 = -1e30f;
#pragma unroll
            for (int j = 0; j < 8; j++) {
                mt0 = fmaxf(mt0, fmaxf(sc[j][0], sc[j][1]));
                mt1 = fmaxf(mt1, fmaxf(sc[j][2], sc[j][3]));
            }
            mt0 = fmaxf(mt0, __shfl_xor_sync(0xffffffffu, mt0, 1));
            mt0 = fmaxf(mt0, __shfl_xor_sync(0xffffffffu, mt0, 2));
            mt1 = fmaxf(mt1, __shfl_xor_sync(0xffffffffu, mt1, 1));
            mt1 = fmaxf(mt1, __shfl_xor_sync(0xffffffffu, mt1, 2));

            float mn0 = fmaxf(m0, mt0), mn1 = fmaxf(m1, mt1);
            float corr0 = __expf(m0 - mn0), corr1 = __expf(m1 - mn1);

            float ps0 = 0.f, ps1 = 0.f;
#pragma unroll
            for (int j = 0; j < 8; j++) {
                float p0 = __expf(sc[j][0] - mn0);
                float p1 = __expf(sc[j][1] - mn0);
                float p2 = __expf(sc[j][2] - mn1);
                float p3 = __expf(sc[j][3] - mn1);
                sc[j][0] = p0; sc[j][1] = p1; sc[j][2] = p2; sc[j][3] = p3;
                ps0 += p0 + p1; ps1 += p2 + p3;
            }
            ps0 += __shfl_xor_sync(0xffffffffu, ps0, 1);
            ps0 += __shfl_xor_sync(0xffffffffu, ps0, 2);
            ps1 += __shfl_xor_sync(0xffffffffu, ps1, 1);
            ps1 += __shfl_xor_sync(0xffffffffu, ps1, 2);

            l0 = l0 * corr0 + ps0; m0 = mn0;
            l1 = l1 * corr1 + ps1; m1 = mn1;
#pragma unroll
            for (int j = 0; j < 8; j++) {
                o[j][0] *= corr0; o[j][1] *= corr0;
                o[j][2] *= corr1; o[j][3] *= corr1;
            }

            // ---- O += P V (3-split) ----
#pragma unroll
            for (int ks = 0; ks < 4; ks++) {
                uint32_t ph[4], pl[4];
                ph[0] = pack_hi2(sc[2*ks][0],   sc[2*ks][1]);
                ph[1] = pack_hi2(sc[2*ks][2],   sc[2*ks][3]);
                ph[2] = pack_hi2(sc[2*ks+1][0], sc[2*ks+1][1]);
                ph[3] = pack_hi2(sc[2*ks+1][2], sc[2*ks+1][3]);
                pl[0] = pack_lo2(sc[2*ks][0],   sc[2*ks][1]);
                pl[1] = pack_lo2(sc[2*ks][2],   sc[2*ks][3]);
                pl[2] = pack_lo2(sc[2*ks+1][0], sc[2*ks+1][1]);
                pl[3] = pack_lo2(sc[2*ks+1][2], sc[2*ks+1][3]);
#pragma unroll
                for (int j = 0; j < 4; j++) {
                    uint32_t bh[4], bl[4];
                    int row = ks * 16 + (lane & 15);
                    int ch = j * 2 + (lane >> 4);
                    uint32_t off = row * 128 + ((ch ^ (row & 7)) * 16);
                    LDSM_X4T(bh, svh + off);
                    LDSM_X4T(bl, svl + off);
                    MMA16816(o[2*j],     ph, (&bh[0]));
                    MMA16816(o[2*j],     ph, (&bl[0]));
                    MMA16816(o[2*j],     pl, (&bh[0]));
                    MMA16816(o[2*j + 1], ph, (&bh[2]));
                    MMA16816(o[2*j + 1], ph, (&bl[2]));
                    MMA16816(o[2*j + 1], pl, (&bh[2]));
                }
            }
        }
        __syncthreads();
    }

    // ---- normalize + split-store ----
    float inv0 = 1.f / l0, inv1 = 1.f / l1;
    const int row0 = b * SEQ + qt * 128 + wid * 16 + (lane >> 2);
#pragma unroll
    for (int j = 0; j < 8; j++) {
        float a0 = o[j][0] * inv0, a1 = o[j][1] * inv0;
        float a2 = o[j][2] * inv1, a3 = o[j][3] * inv1;
        size_t off0 = (size_t)row0 * EMB + h * HDIM + j * 8 + (lane & 3) * 2;
        size_t off1 = off0 + (size_t)8 * EMB;
        *(uint32_t*)&Ohi[off0] = pack_hi2(a0, a1);
        *(uint32_t*)&Olo[off0] = pack_lo2(a0, a1);
        *(uint32_t*)&Ohi[off1] = pack_hi2(a2, a3);
        *(uint32_t*)&Olo[off1] = pack_lo2(a2, a3);
    }
}

// ======================= Scratch =======================
__device__ __nv_bfloat16 g_xhi[TOK * EMB], g_xlo[TOK * EMB];
__device__ __nv_bfloat16 g_qhi[TOK * EMB], g_qlo[TOK * EMB];
__device__ __nv_bfloat16 g_khi[TOK * EMB], g_klo[TOK * EMB];
__device__ __nv_bfloat16 g_vhi[TOK * EMB], g_vlo[TOK * EMB];
__device__ __nv_bfloat16 g_ahi[TOK * EMB], g_alo[TOK * EMB];
__device__ __nv_bfloat16 g_wqhi[EMB * EMB], g_wqlo[EMB * EMB];
__device__ __nv_bfloat16 g_wkhi[EMB * EMB], g_wklo[EMB * EMB];
__device__ __nv_bfloat16 g_wvhi[EMB * EMB], g_wvlo[EMB * EMB];
__device__ __nv_bfloat16 g_wohi[EMB * EMB], g_wolo[EMB * EMB];

extern "C" void kernel_launch(void* const* d_in, const int* in_sizes, int n_in,
                              void* d_out, int out_size) {
    const float* x  = (const float*)d_in[0];
    const float* Wq = (const float*)d_in[2];
    const float* Wk = (const float*)d_in[3];
    const float* Wv = (const float*)d_in[4];
    const float* Wo = (const float*)d_in[5];
    float* out = (float*)d_out;

    __nv_bfloat16 *xhi, *xlo, *qhi, *qlo, *khi, *klo, *vhi, *vlo, *ahi, *alo;
    __nv_bfloat16 *wqhi, *wqlo, *wkhi, *wklo, *wvhi, *wvlo, *wohi, *wolo;
    cudaGetSymbolAddress((void**)&xhi, g_xhi);   cudaGetSymbolAddress((void**)&xlo, g_xlo);
    cudaGetSymbolAddress((void**)&qhi, g_qhi);   cudaGetSymbolAddress((void**)&qlo, g_qlo);
    cudaGetSymbolAddress((void**)&khi, g_khi);   cudaGetSymbolAddress((void**)&klo, g_klo);
    cudaGetSymbolAddress((void**)&vhi, g_vhi);   cudaGetSymbolAddress((void**)&vlo, g_vlo);
    cudaGetSymbolAddress((void**)&ahi, g_ahi);   cudaGetSymbolAddress((void**)&alo, g_alo);
    cudaGetSymbolAddress((void**)&wqhi, g_wqhi); cudaGetSymbolAddress((void**)&wqlo, g_wqlo);
    cudaGetSymbolAddress((void**)&wkhi, g_wkhi); cudaGetSymbolAddress((void**)&wklo, g_wklo);
    cudaGetSymbolAddress((void**)&wvhi, g_wvhi); cudaGetSymbolAddress((void**)&wvlo, g_wvlo);
    cudaGetSymbolAddress((void**)&wohi, g_wohi); cudaGetSymbolAddress((void**)&wolo, g_wolo);

    static bool attrs_set = false;
    if (!attrs_set) {
        cudaFuncSetAttribute(gemm_qkv_kernel,
                             cudaFuncAttributeMaxDynamicSharedMemorySize, GEMM_SMEM);
        cudaFuncSetAttribute(gemm_o_kernel,
                             cudaFuncAttributeMaxDynamicSharedMemorySize, GEMM_SMEM);
        cudaFuncSetAttribute(attn_mma_kernel,
                             cudaFuncAttributeMaxDynamicSharedMemorySize, ATTN_SMEM);
        attrs_set = true;
    }

    // one fused conversion launch: x (y=0) + 4 weights (y=1..4)
    const int XB = (TOK * EMB / 4 + 255) / 256;  // 4096 blocks
    dim3 cvtGrid(XB, 5);
    cvt_all_kernel<<<cvtGrid, 256>>>(x, Wq, Wk, Wv, Wo,
                                     xhi, xlo, wqhi, wqlo, wkhi, wklo,
                                     wvhi, wvlo, wohi, wolo);

    dim3 qkvGrid(EMB / NT, TOK / MT, 3);   // (8, 32, 3)
    gemm_qkv_kernel<<<qkvGrid, 256, GEMM_SMEM>>>(xhi, xlo, wqhi, wqlo, wkhi, wklo,
                                                 wvhi, wvlo, qhi, qlo, khi, klo, vhi, vlo);

    dim3 attnGrid(SEQ / 128, HEADS, BATCH);   // (16, 16, 2)
    attn_mma_kernel<<<attnGrid, 256, ATTN_SMEM>>>(qhi, qlo, khi, klo, vhi, vlo, ahi, alo);

    dim3 oGrid(EMB / NT, TOK / MT);   // (8, 32)
    gemm_o_kernel<<<oGrid, 256, GEMM_SMEM>>>(ahi, alo, wohi, wolo, out);
}

// round 8
// speedup vs baseline: 13.3314x; 1.1114x over previous
#include <cuda_runtime.h>
#include <cuda_bf16.h>
#include <cuda_fp16.h>
#include <cstdint>
#include <math.h>

#define BATCH 2
#define SEQ   2048
#define EMB   1024
#define HEADS 16
#define HDIM  64
#define TOK   (BATCH * SEQ)   // 4096

// ======================= PTX helpers (sm_80-era ISA only) =======================
__device__ __forceinline__ uint32_t smem_u32(const void* p) {
    uint32_t a;
    asm("{ .reg .u64 t; cvta.to.shared.u64 t, %1; cvt.u32.u64 %0, t; }"
        : "=r"(a) : "l"(p));
    return a;
}

#define LDSM_X4(r, a) \
    asm volatile("ldmatrix.sync.aligned.m8n8.x4.shared.b16 {%0,%1,%2,%3}, [%4];" \
                 : "=r"((r)[0]), "=r"((r)[1]), "=r"((r)[2]), "=r"((r)[3]) : "r"(a))

#define LDSM_X4T(r, a) \
    asm volatile("ldmatrix.sync.aligned.m8n8.x4.trans.shared.b16 {%0,%1,%2,%3}, [%4];" \
                 : "=r"((r)[0]), "=r"((r)[1]), "=r"((r)[2]), "=r"((r)[3]) : "r"(a))

#define MMA16816(d, a, b) \
    asm volatile("mma.sync.aligned.m16n8k16.row.col.f32.bf16.bf16.f32 " \
                 "{%0,%1,%2,%3}, {%4,%5,%6,%7}, {%8,%9}, {%0,%1,%2,%3};" \
                 : "+f"((d)[0]), "+f"((d)[1]), "+f"((d)[2]), "+f"((d)[3]) \
                 : "r"((a)[0]), "r"((a)[1]), "r"((a)[2]), "r"((a)[3]), \
                   "r"((b)[0]), "r"((b)[1]))

#define MMA16816H(d, a, b) \
    asm volatile("mma.sync.aligned.m16n8k16.row.col.f32.f16.f16.f32 " \
                 "{%0,%1,%2,%3}, {%4,%5,%6,%7}, {%8,%9}, {%0,%1,%2,%3};" \
                 : "+f"((d)[0]), "+f"((d)[1]), "+f"((d)[2]), "+f"((d)[3]) \
                 : "r"((a)[0]), "r"((a)[1]), "r"((a)[2]), "r"((a)[3]), \
                   "r"((b)[0]), "r"((b)[1]))

#define CP_ASYNC16(saddr, gaddr) \
    asm volatile("cp.async.cg.shared.global [%0], [%1], 16;" :: "r"(saddr), "l"(gaddr))
#define CP_COMMIT() asm volatile("cp.async.commit_group;" ::: "memory")
#define CP_WAIT1() asm volatile("cp.async.wait_group 1;" ::: "memory")
#define CP_WAIT0() asm volatile("cp.async.wait_group 0;" ::: "memory")

__device__ __forceinline__ uint32_t pack_hi2(float x, float y) {
    __nv_bfloat162 t = __halves2bfloat162(__float2bfloat16(x), __float2bfloat16(y));
    return *(uint32_t*)&t;
}
__device__ __forceinline__ uint32_t pack_lo2(float x, float y) {
    __nv_bfloat16 hx = __float2bfloat16(x), hy = __float2bfloat16(y);
    __nv_bfloat162 t = __halves2bfloat162(__float2bfloat16(x - __bfloat162float(hx)),
                                          __float2bfloat16(y - __bfloat162float(hy)));
    return *(uint32_t*)&t;
}
__device__ __forceinline__ uint32_t packh2(float x, float y) {
    __half2 t = __floats2half2_rn(x, y);
    return *(uint32_t*)&t;
}
__device__ __forceinline__ uint32_t packh_lo2(float x, float y) {
    __half hx = __float2half_rn(x), hy = __float2half_rn(y);
    __half2 t = __halves2half2(__float2half_rn(x - __half2float(hx)),
                               __float2half_rn(y - __half2float(hy)));
    return *(uint32_t*)&t;
}

// ======================= fused fp32 -> (bf16 hi, lo) split: x + 4 weights =======================
__global__ void cvt_all_kernel(const float* __restrict__ x,
                               const float* __restrict__ w0, const float* __restrict__ w1,
                               const float* __restrict__ w2, const float* __restrict__ w3,
                               __nv_bfloat16* __restrict__ xhi, __nv_bfloat16* __restrict__ xlo,
                               __nv_bfloat16* __restrict__ h0, __nv_bfloat16* __restrict__ l0,
                               __nv_bfloat16* __restrict__ h1, __nv_bfloat16* __restrict__ l1,
                               __nv_bfloat16* __restrict__ h2, __nv_bfloat16* __restrict__ l2,
                               __nv_bfloat16* __restrict__ h3, __nv_bfloat16* __restrict__ l3) {
    const int z = blockIdx.y;
    const float* in;
    __nv_bfloat16 *hi, *lo;
    int n4;
    switch (z) {
        case 0: in = x;  hi = xhi; lo = xlo; n4 = TOK * EMB / 4; break;
        case 1: in = w0; hi = h0;  lo = l0;  n4 = EMB * EMB / 4; break;
        case 2: in = w1; hi = h1;  lo = l1;  n4 = EMB * EMB / 4; break;
        case 3: in = w2; hi = h2;  lo = l2;  n4 = EMB * EMB / 4; break;
        default: in = w3; hi = h3; lo = l3;  n4 = EMB * EMB / 4; break;
    }
    int i = blockIdx.x * blockDim.x + threadIdx.x;
    if (i >= n4) return;
    float4 v = *(const float4*)(in + i * 4);
    *(uint32_t*)(hi + i * 4)     = pack_hi2(v.x, v.y);
    *(uint32_t*)(hi + i * 4 + 2) = pack_hi2(v.z, v.w);
    *(uint32_t*)(lo + i * 4)     = pack_lo2(v.x, v.y);
    *(uint32_t*)(lo + i * 4 + 2) = pack_lo2(v.z, v.w);
}

// ======================= mma.sync split-bf16 GEMM: 128x64 tile, 2 CTAs/SM =======================
#define MT 128
#define NT 64
#define KT 64
#define NKTILE (EMB / KT)             // 16
#define TILE_A (128 * 128)            // 16KB
#define TILE_B (64 * 128)             // 8KB
#define STAGE_BYTES (2 * TILE_A + 2 * TILE_B)  // 48KB
#define GEMM_SMEM (2 * STAGE_BYTES)   // 96KB -> 2 CTAs/SM

// Epilogue modes: 0 = fp32 C, 1 = bf16 hi/lo split, 2 = fp16 hi/lo split
__device__ __forceinline__ void gemm_core(
        const __nv_bfloat16* __restrict__ Ahi, const __nv_bfloat16* __restrict__ Alo,
        const __nv_bfloat16* __restrict__ Bhi, const __nv_bfloat16* __restrict__ Blo,
        float* __restrict__ C, void* __restrict__ Chi, void* __restrict__ Clo,
        int mode, const uint32_t smb, int rowBase, int colBase) {
    const int tid = threadIdx.x;
    const int lane = tid & 31;
    const int wid = tid >> 5;
    const int wm = wid >> 1;          // 0..3 (32 rows each)
    const int wn = wid & 1;           // 0..1 (32 cols each)

    float acc[2][4][4];
#pragma unroll
    for (int mi = 0; mi < 2; mi++)
#pragma unroll
        for (int ni = 0; ni < 4; ni++)
#pragma unroll
            for (int j = 0; j < 4; j++) acc[mi][ni][j] = 0.f;

    auto load_stage = [&](int s, int kt) {
        const int k0 = kt * KT;
        uint32_t sb = smb + s * STAGE_BYTES;
        // A: hi+lo, 128 rows x 8 chunks each = 2048 chunks
#pragma unroll
        for (int it = 0; it < 8; it++) {
            int idx = tid + it * 256;
            int arr = idx >> 10;
            int rc  = idx & 1023;
            int row = rc >> 3;
            int ch  = rc & 7;
            uint32_t soff = sb + arr * TILE_A + row * 128 + ((ch ^ (row & 7)) * 16);
            const __nv_bfloat16* src = arr ? Alo : Ahi;
            CP_ASYNC16(soff, src + (size_t)(rowBase + row) * EMB + k0 + ch * 8);
        }
        // B: hi+lo, 64 rows x 8 chunks each = 1024 chunks
#pragma unroll
        for (int it = 0; it < 4; it++) {
            int idx = tid + it * 256;
            int arr = idx >> 9;
            int rc  = idx & 511;
            int row = rc >> 3;
            int ch  = rc & 7;
            uint32_t soff = sb + 2 * TILE_A + arr * TILE_B + row * 128 + ((ch ^ (row & 7)) * 16);
            const __nv_bfloat16* src = arr ? Blo : Bhi;
            CP_ASYNC16(soff, src + (size_t)(colBase + row) * EMB + k0 + ch * 8);
        }
        CP_COMMIT();
    };

    auto compute_stage = [&](int s) {
        const uint32_t sah = smb + s * STAGE_BYTES;
        const uint32_t sal = sah + TILE_A;
        const uint32_t sbh = sah + 2 * TILE_A;
        const uint32_t sbl = sbh + TILE_B;
#pragma unroll
        for (int ks = 0; ks < 4; ks++) {
            uint32_t ahi[2][4], alo[2][4];
#pragma unroll
            for (int mi = 0; mi < 2; mi++) {
                int row = wm * 32 + mi * 16 + (lane & 15);
                int ch = ks * 2 + (lane >> 4);
                uint32_t off = row * 128 + ((ch ^ (row & 7)) * 16);
                LDSM_X4(ahi[mi], sah + off);
                LDSM_X4(alo[mi], sal + off);
            }
            uint32_t bhi[4][2], blo[4][2];
#pragma unroll
            for (int nip = 0; nip < 2; nip++) {
                int ni = nip * 2;
                int row = wn * 32 + (ni + (lane >> 4)) * 8 + (lane & 7);
                int ch = ks * 2 + ((lane >> 3) & 1);
                uint32_t off = row * 128 + ((ch ^ (row & 7)) * 16);
                uint32_t t4[4];
                LDSM_X4(t4, sbh + off);
                bhi[ni][0] = t4[0]; bhi[ni][1] = t4[1];
                bhi[ni + 1][0] = t4[2]; bhi[ni + 1][1] = t4[3];
                LDSM_X4(t4, sbl + off);
                blo[ni][0] = t4[0]; blo[ni][1] = t4[1];
                blo[ni + 1][0] = t4[2]; blo[ni + 1][1] = t4[3];
            }
#pragma unroll
            for (int mi = 0; mi < 2; mi++)
#pragma unroll
                for (int ni = 0; ni < 4; ni++) {
                    MMA16816(acc[mi][ni], ahi[mi], bhi[ni]);
                    MMA16816(acc[mi][ni], ahi[mi], blo[ni]);
                    MMA16816(acc[mi][ni], alo[mi], bhi[ni]);
                }
        }
    };

    load_stage(0, 0);
    load_stage(1, 1);
    for (int t = 0; t < NKTILE; t++) {
        if (t < NKTILE - 2) CP_WAIT1(); else CP_WAIT0();
        __syncthreads();
        compute_stage(t & 1);
        __syncthreads();
        if (t + 2 < NKTILE) load_stage(t & 1, t + 2);
    }

#pragma unroll
    for (int mi = 0; mi < 2; mi++) {
#pragma unroll
        for (int ni = 0; ni < 4; ni++) {
            int row = rowBase + wm * 32 + mi * 16 + (lane >> 2);
            int col = colBase + wn * 32 + ni * 8 + (lane & 3) * 2;
            size_t o0 = (size_t)row * EMB + col;
            size_t o1 = (size_t)(row + 8) * EMB + col;
            if (mode == 0) {
                *(float2*)&C[o0] = make_float2(acc[mi][ni][0], acc[mi][ni][1]);
                *(float2*)&C[o1] = make_float2(acc[mi][ni][2], acc[mi][ni][3]);
            } else if (mode == 1) {
                __nv_bfloat16* ch = (__nv_bfloat16*)Chi;
                __nv_bfloat16* cl = (__nv_bfloat16*)Clo;
                *(uint32_t*)&ch[o0] = pack_hi2(acc[mi][ni][0], acc[mi][ni][1]);
                *(uint32_t*)&cl[o0] = pack_lo2(acc[mi][ni][0], acc[mi][ni][1]);
                *(uint32_t*)&ch[o1] = pack_hi2(acc[mi][ni][2], acc[mi][ni][3]);
                *(uint32_t*)&cl[o1] = pack_lo2(acc[mi][ni][2], acc[mi][ni][3]);
            } else {
                __half* ch = (__half*)Chi;
                __half* cl = (__half*)Clo;
                *(uint32_t*)&ch[o0] = packh2(acc[mi][ni][0], acc[mi][ni][1]);
                *(uint32_t*)&cl[o0] = packh_lo2(acc[mi][ni][0], acc[mi][ni][1]);
                *(uint32_t*)&ch[o1] = packh2(acc[mi][ni][2], acc[mi][ni][3]);
                *(uint32_t*)&cl[o1] = packh_lo2(acc[mi][ni][2], acc[mi][ni][3]);
            }
        }
    }
}

// Fused QKV: blockIdx.z selects weight/output set. V (z=2) emits fp16 split.
__global__ void __launch_bounds__(256, 2)
gemm_qkv_kernel(const __nv_bfloat16* __restrict__ xhi, const __nv_bfloat16* __restrict__ xlo,
                const __nv_bfloat16* __restrict__ wqh, const __nv_bfloat16* __restrict__ wql,
                const __nv_bfloat16* __restrict__ wkh, const __nv_bfloat16* __restrict__ wkl,
                const __nv_bfloat16* __restrict__ wvh, const __nv_bfloat16* __restrict__ wvl,
                __nv_bfloat16* __restrict__ qh, __nv_bfloat16* __restrict__ ql,
                __nv_bfloat16* __restrict__ kh, __nv_bfloat16* __restrict__ kl,
                __half* __restrict__ vh, __half* __restrict__ vl) {
    extern __shared__ char sm[];
    const int z = blockIdx.z;
    const __nv_bfloat16* Bh = (z == 0) ? wqh : (z == 1) ? wkh : wvh;
    const __nv_bfloat16* Bl = (z == 0) ? wql : (z == 1) ? wkl : wvl;
    void* Ch = (z == 0) ? (void*)qh : (z == 1) ? (void*)kh : (void*)vh;
    void* Cl = (z == 0) ? (void*)ql : (z == 1) ? (void*)kl : (void*)vl;
    int mode = (z == 2) ? 2 : 1;
    gemm_core(xhi, xlo, Bh, Bl, nullptr, Ch, Cl, mode, smem_u32(sm),
              blockIdx.y * MT, blockIdx.x * NT);
}

__global__ void __launch_bounds__(256, 2)
gemm_o_kernel(const __nv_bfloat16* __restrict__ ahi, const __nv_bfloat16* __restrict__ alo,
              const __nv_bfloat16* __restrict__ woh, const __nv_bfloat16* __restrict__ wol,
              float* __restrict__ out) {
    extern __shared__ char sm[];
    gemm_core(ahi, alo, woh, wol, out, nullptr, nullptr, 0, smem_u32(sm),
              blockIdx.y * MT, blockIdx.x * NT);
}

// ======================= Flash attention: QK bf16 3-term, PV fp16 2-term =======================
#define ATILE (128 * 128)          // 16KB
#define KVTILE (64 * 128)          // 8KB
#define KVSTAGE (4 * KVTILE)       // 32KB
#define Q_OFF 0
#define KV_OFF (2 * ATILE)         // 32KB
#define ATTN_SMEM (2 * ATILE + 2 * KVSTAGE)  // 96KB

__global__ void __launch_bounds__(256, 1)
attn_mma_kernel(const __nv_bfloat16* __restrict__ Qhi, const __nv_bfloat16* __restrict__ Qlo,
                const __nv_bfloat16* __restrict__ Khi, const __nv_bfloat16* __restrict__ Klo,
                const __half* __restrict__ Vhi, const __half* __restrict__ Vlo,
                __nv_bfloat16* __restrict__ Ohi, __nv_bfloat16* __restrict__ Olo) {
    extern __shared__ char sm[];
    const uint32_t smb = smem_u32(sm);

    const int tid = threadIdx.x;
    const int lane = tid & 31;
    const int wid = tid >> 5;
    const int qt = gridDim.x - 1 - blockIdx.x;
    const int h  = blockIdx.y;
    const int b  = blockIdx.z;

    const size_t base = (size_t)b * SEQ * EMB + (size_t)h * HDIM;
    const __nv_bfloat16* qh = Qhi + base;
    const __nv_bfloat16* ql = Qlo + base;
    const __nv_bfloat16* kh = Khi + base;
    const __nv_bfloat16* kl = Klo + base;
    const __half* vh = Vhi + base;
    const __half* vl = Vlo + base;

    auto load_kv = [&](int s, int kt) {
        const void* bases[4] = {kh, kl, vh, vl};
#pragma unroll
        for (int it = 0; it < 8; it++) {
            int idx = tid + it * 256;
            int arr = idx >> 9;
            int rc  = idx & 511;
            int row = rc >> 3;
            int ch  = rc & 7;
            uint32_t soff = smb + KV_OFF + s * KVSTAGE + arr * KVTILE
                          + row * 128 + ((ch ^ (row & 7)) * 16);
            const char* g = (const char*)bases[arr]
                          + ((size_t)(kt * 64 + row) * EMB + ch * 8) * 2;
            CP_ASYNC16(soff, g);
        }
        CP_COMMIT();
    };

    // group 0: Q tile
#pragma unroll
    for (int it = 0; it < 8; it++) {
        int idx = tid + it * 256;
        int arr = idx >> 10;
        int rc  = idx & 1023;
        int row = rc >> 3;
        int ch  = rc & 7;
        uint32_t soff = smb + Q_OFF + arr * ATILE + row * 128 + ((ch ^ (row & 7)) * 16);
        const __nv_bfloat16* src = (arr == 0) ? qh : ql;
        CP_ASYNC16(soff, src + (size_t)(qt * 128 + row) * EMB + ch * 8);
    }
    CP_COMMIT();

    const int ktmax = 2 * qt + 1;
    load_kv(0, 0);

    float o[8][4];
#pragma unroll
    for (int j = 0; j < 8; j++)
#pragma unroll
        for (int c = 0; c < 4; c++) o[j][c] = 0.f;
    float m0 = -1e30f, m1 = -1e30f, l0 = 0.f, l1 = 0.f;

    const float sscale = 0.125f;
    const int qrow0 = qt * 128 + wid * 16 + (lane >> 2);
    const uint32_t sqh = smb + Q_OFF;
    const uint32_t sql = smb + Q_OFF + ATILE;

    for (int kt = 0; kt <= ktmax; kt++) {
        if (kt < ktmax) { load_kv((kt + 1) & 1, kt + 1); CP_WAIT1(); }
        else           { CP_WAIT0(); }
        __syncthreads();

        bool active = (kt * 64 <= qt * 128 + wid * 16 + 15);
        if (active) {
            const int s = kt & 1;
            const uint32_t skh = smb + KV_OFF + s * KVSTAGE + 0 * KVTILE;
            const uint32_t skl = smb + KV_OFF + s * KVSTAGE + 1 * KVTILE;
            const uint32_t svh = smb + KV_OFF + s * KVSTAGE + 2 * KVTILE;
            const uint32_t svl = smb + KV_OFF + s * KVSTAGE + 3 * KVTILE;

            // ---- S = Q K^T (bf16 3-split) ----
            float sc[8][4];
#pragma unroll
            for (int j = 0; j < 8; j++)
#pragma unroll
                for (int c = 0; c < 4; c++) sc[j][c] = 0.f;

#pragma unroll
            for (int ks = 0; ks < 4; ks++) {
                uint32_t ah[4], al[4];
                {
                    int row = wid * 16 + (lane & 15);
                    int ch = ks * 2 + (lane >> 4);
                    uint32_t off = row * 128 + ((ch ^ (row & 7)) * 16);
                    LDSM_X4(ah, sqh + off);
                    LDSM_X4(al, sql + off);
                }
#pragma unroll
                for (int jp = 0; jp < 4; jp++) {
                    int j = jp * 2;
                    int row = (j + (lane >> 4)) * 8 + (lane & 7);
                    int ch = ks * 2 + ((lane >> 3) & 1);
                    uint32_t off = row * 128 + ((ch ^ (row & 7)) * 16);
                    uint32_t bh[4], bl[4];
                    LDSM_X4(bh, skh + off);
                    LDSM_X4(bl, skl + off);
                    MMA16816(sc[j],     ah, (&bh[0]));
                    MMA16816(sc[j],     ah, (&bl[0]));
                    MMA16816(sc[j],     al, (&bh[0]));
                    MMA16816(sc[j + 1], ah, (&bh[2]));
                    MMA16816(sc[j + 1], ah, (&bl[2]));
                    MMA16816(sc[j + 1], al, (&bh[2]));
                }
            }

            // ---- scale + causal mask ----
            bool diag = (kt * 64 + 63 > qt * 128 + wid * 16);
#pragma unroll
            for (int j = 0; j < 8; j++) {
                int col = kt * 64 + j * 8 + (lane & 3) * 2;
#pragma unroll
                for (int c = 0; c < 4; c++) {
                    float v = sc[j][c] * sscale;
                    if (diag) {
                        int cc = col + (c & 1);
                        int rr = qrow0 + ((c >= 2) ? 8 : 0);
                        if (cc > rr) v = -1e30f;
                    }
                    sc[j][c] = v;
                }
            }

            // ---- online softmax ----
            float mt0 = -1e30f, mt1 = -1e30f;
#pragma unroll
            for (int j = 0; j < 8; j++) {
                mt0 = fmaxf(mt0, fmaxf(sc[j][0], sc[j][1]));
                mt1 = fmaxf(mt1, fmaxf(sc[j][2], sc[j][3]));
            }
            mt0 = fmaxf(mt0, __shfl_xor_sync(0xffffffffu, mt0, 1));
            mt0 = fmaxf(mt0, __shfl_xor_sync(0xffffffffu, mt0, 2));
            mt1 = fmaxf(mt1, __shfl_xor_sync(0xffffffffu, mt1, 1));
            mt1 = fmaxf(mt1, __shfl_xor_sync(0xffffffffu, mt1, 2));

            float mn0 = fmaxf(m0, mt0), mn1 = fmaxf(m1, mt1);
            float corr0 = __expf(m0 - mn0), corr1 = __expf(m1 - mn1);

            float ps0 = 0.f, ps1 = 0.f;
#pragma unroll
            for (int j = 0; j < 8; j++) {
                float p0 = __expf(sc[j][0] - mn0);
                float p1 = __expf(sc[j][1] - mn0);
                float p2 = __expf(sc[j][2] - mn1);
                float p3 = __expf(sc[j][3] - mn1);
                sc[j][0] = p0; sc[j][1] = p1; sc[j][2] = p2; sc[j][3] = p3;
                ps0 += p0 + p1; ps1 += p2 + p3;
            }
            ps0 += __shfl_xor_sync(0xffffffffu, ps0, 1);
            ps0 += __shfl_xor_sync(0xffffffffu, ps0, 2);
            ps1 += __shfl_xor_sync(0xffffffffu, ps1, 1);
            ps1 += __shfl_xor_sync(0xffffffffu, ps1, 2);

            l0 = l0 * corr0 + ps0; m0 = mn0;
            l1 = l1 * corr1 + ps1; m1 = mn1;
#pragma unroll
            for (int j = 0; j < 8; j++) {
                o[j][0] *= corr0; o[j][1] *= corr0;
                o[j][2] *= corr1; o[j][3] *= corr1;
            }

            // ---- O += P V (fp16 2-term: P single fp16, V hi/lo fp16) ----
#pragma unroll
            for (int ks = 0; ks < 4; ks++) {
                uint32_t ph[4];
                ph[0] = packh2(sc[2*ks][0],   sc[2*ks][1]);
                ph[1] = packh2(sc[2*ks][2],   sc[2*ks][3]);
                ph[2] = packh2(sc[2*ks+1][0], sc[2*ks+1][1]);
                ph[3] = packh2(sc[2*ks+1][2], sc[2*ks+1][3]);
#pragma unroll
                for (int j = 0; j < 4; j++) {
                    uint32_t bh[4], bl[4];
                    int row = ks * 16 + (lane & 15);
                    int ch = j * 2 + (lane >> 4);
                    uint32_t off = row * 128 + ((ch ^ (row & 7)) * 16);
                    LDSM_X4T(bh, svh + off);
                    LDSM_X4T(bl, svl + off);
                    MMA16816H(o[2*j],     ph, (&bh[0]));
                    MMA16816H(o[2*j],     ph, (&bl[0]));
                    MMA16816H(o[2*j + 1], ph, (&bh[2]));
                    MMA16816H(o[2*j + 1], ph, (&bl[2]));
                }
            }
        }
        __syncthreads();
    }

    // ---- normalize + split-store (bf16 for Wo GEMM) ----
    float inv0 = 1.f / l0, inv1 = 1.f / l1;
    const int row0 = b * SEQ + qt * 128 + wid * 16 + (lane >> 2);
#pragma unroll
    for (int j = 0; j < 8; j++) {
        float a0 = o[j][0] * inv0, a1 = o[j][1] * inv0;
        float a2 = o[j][2] * inv1, a3 = o[j][3] * inv1;
        size_t off0 = (size_t)row0 * EMB + h * HDIM + j * 8 + (lane & 3) * 2;
        size_t off1 = off0 + (size_t)8 * EMB;
        *(uint32_t*)&Ohi[off0] = pack_hi2(a0, a1);
        *(uint32_t*)&Olo[off0] = pack_lo2(a0, a1);
        *(uint32_t*)&Ohi[off1] = pack_hi2(a2, a3);
        *(uint32_t*)&Olo[off1] = pack_lo2(a2, a3);
    }
}

// ======================= Scratch =======================
__device__ __nv_bfloat16 g_xhi[TOK * EMB], g_xlo[TOK * EMB];
__device__ __nv_bfloat16 g_qhi[TOK * EMB], g_qlo[TOK * EMB];
__device__ __nv_bfloat16 g_khi[TOK * EMB], g_klo[TOK * EMB];
__device__ __half        g_vhi[TOK * EMB], g_vlo[TOK * EMB];
__device__ __nv_bfloat16 g_ahi[TOK * EMB], g_alo[TOK * EMB];
__device__ __nv_bfloat16 g_wqhi[EMB * EMB], g_wqlo[EMB * EMB];
__device__ __nv_bfloat16 g_wkhi[EMB * EMB], g_wklo[EMB * EMB];
__device__ __nv_bfloat16 g_wvhi[EMB * EMB], g_wvlo[EMB * EMB];
__device__ __nv_bfloat16 g_wohi[EMB * EMB], g_wolo[EMB * EMB];

extern "C" void kernel_launch(void* const* d_in, const int* in_sizes, int n_in,
                              void* d_out, int out_size) {
    const float* x  = (const float*)d_in[0];
    const float* Wq = (const float*)d_in[2];
    const float* Wk = (const float*)d_in[3];
    const float* Wv = (const float*)d_in[4];
    const float* Wo = (const float*)d_in[5];
    float* out = (float*)d_out;

    __nv_bfloat16 *xhi, *xlo, *qhi, *qlo, *khi, *klo, *ahi, *alo;
    __half *vhi, *vlo;
    __nv_bfloat16 *wqhi, *wqlo, *wkhi, *wklo, *wvhi, *wvlo, *wohi, *wolo;
    cudaGetSymbolAddress((void**)&xhi, g_xhi);   cudaGetSymbolAddress((void**)&xlo, g_xlo);
    cudaGetSymbolAddress((void**)&qhi, g_qhi);   cudaGetSymbolAddress((void**)&qlo, g_qlo);
    cudaGetSymbolAddress((void**)&khi, g_khi);   cudaGetSymbolAddress((void**)&klo, g_klo);
    cudaGetSymbolAddress((void**)&vhi, g_vhi);   cudaGetSymbolAddress((void**)&vlo, g_vlo);
    cudaGetSymbolAddress((void**)&ahi, g_ahi);   cudaGetSymbolAddress((void**)&alo, g_alo);
    cudaGetSymbolAddress((void**)&wqhi, g_wqhi); cudaGetSymbolAddress((void**)&wqlo, g_wqlo);
    cudaGetSymbolAddress((void**)&wkhi, g_wkhi); cudaGetSymbolAddress((void**)&wklo, g_wklo);
    cudaGetSymbolAddress((void**)&wvhi, g_wvhi); cudaGetSymbolAddress((void**)&wvlo, g_wvlo);
    cudaGetSymbolAddress((void**)&wohi, g_wohi); cudaGetSymbolAddress((void**)&wolo, g_wolo);

    static bool attrs_set = false;
    if (!attrs_set) {
        cudaFuncSetAttribute(gemm_qkv_kernel,
                             cudaFuncAttributeMaxDynamicSharedMemorySize, GEMM_SMEM);
        cudaFuncSetAttribute(gemm_o_kernel,
                             cudaFuncAttributeMaxDynamicSharedMemorySize, GEMM_SMEM);
        cudaFuncSetAttribute(attn_mma_kernel,
                             cudaFuncAttributeMaxDynamicSharedMemorySize, ATTN_SMEM);
        attrs_set = true;
    }

    const int XB = (TOK * EMB / 4 + 255) / 256;
    dim3 cvtGrid(XB, 5);
    cvt_all_kernel<<<cvtGrid, 256>>>(x, Wq, Wk, Wv, Wo,
                                     xhi, xlo, wqhi, wqlo, wkhi, wklo,
                                     wvhi, wvlo, wohi, wolo);

    dim3 qkvGrid(EMB / NT, TOK / MT, 3);   // (16, 32, 3)
    gemm_qkv_kernel<<<qkvGrid, 256, GEMM_SMEM>>>(xhi, xlo, wqhi, wqlo, wkhi, wklo,
                                                 wvhi, wvlo, qhi, qlo, khi, klo, vhi, vlo);

    dim3 attnGrid(SEQ / 128, HEADS, BATCH);   // (16, 16, 2)
    attn_mma_kernel<<<attnGrid, 256, ATTN_SMEM>>>(qhi, qlo, khi, klo, vhi, vlo, ahi, alo);

    dim3 oGrid(EMB / NT, TOK / MT);   // (16, 32)
    gemm_o_kernel<<<oGrid, 256, GEMM_SMEM>>>(ahi, alo, wohi, wolo, out);
}

// round 10
// speedup vs baseline: 16.4021x; 1.2303x over previous
#include <cuda_runtime.h>
#include <cuda_bf16.h>
#include <cuda_fp16.h>
#include <cstdint>
#include <math.h>

#define BATCH 2
#define SEQ   2048
#define EMB   1024
#define HEADS 16
#define HDIM  64
#define TOK   (BATCH * SEQ)   // 4096

// ======================= PTX helpers (sm_80-era ISA only) =======================
__device__ __forceinline__ uint32_t smem_u32(const void* p) {
    uint32_t a;
    asm("{ .reg .u64 t; cvta.to.shared.u64 t, %1; cvt.u32.u64 %0, t; }"
        : "=r"(a) : "l"(p));
    return a;
}

#define LDSM_X4(r, a) \
    asm volatile("ldmatrix.sync.aligned.m8n8.x4.shared.b16 {%0,%1,%2,%3}, [%4];" \
                 : "=r"((r)[0]), "=r"((r)[1]), "=r"((r)[2]), "=r"((r)[3]) : "r"(a))

#define LDSM_X4T(r, a) \
    asm volatile("ldmatrix.sync.aligned.m8n8.x4.trans.shared.b16 {%0,%1,%2,%3}, [%4];" \
                 : "=r"((r)[0]), "=r"((r)[1]), "=r"((r)[2]), "=r"((r)[3]) : "r"(a))

#define MMA16816H(d, a, b) \
    asm volatile("mma.sync.aligned.m16n8k16.row.col.f32.f16.f16.f32 " \
                 "{%0,%1,%2,%3}, {%4,%5,%6,%7}, {%8,%9}, {%0,%1,%2,%3};" \
                 : "+f"((d)[0]), "+f"((d)[1]), "+f"((d)[2]), "+f"((d)[3]) \
                 : "r"((a)[0]), "r"((a)[1]), "r"((a)[2]), "r"((a)[3]), \
                   "r"((b)[0]), "r"((b)[1]))

#define CP_ASYNC16(saddr, gaddr) \
    asm volatile("cp.async.cg.shared.global [%0], [%1], 16;" :: "r"(saddr), "l"(gaddr))
#define CP_COMMIT() asm volatile("cp.async.commit_group;" ::: "memory")
#define CP_WAIT1() asm volatile("cp.async.wait_group 1;" ::: "memory")
#define CP_WAIT0() asm volatile("cp.async.wait_group 0;" ::: "memory")

__device__ __forceinline__ uint32_t packh2(float x, float y) {
    __half2 t = __floats2half2_rn(x, y);
    return *(uint32_t*)&t;
}
__device__ __forceinline__ uint32_t packh_lo2(float x, float y) {
    __half hx = __float2half_rn(x), hy = __float2half_rn(y);
    __half2 t = __halves2half2(__float2half_rn(x - __half2float(hx)),
                               __float2half_rn(y - __half2float(hy)));
    return *(uint32_t*)&t;
}

// ============ fused cvt: x -> fp16 hi/lo split (y=0); weights -> single fp16 (y=1..4) ============
__global__ void cvt_all_kernel(const float* __restrict__ x,
                               const float* __restrict__ w0, const float* __restrict__ w1,
                               const float* __restrict__ w2, const float* __restrict__ w3,
                               __half* __restrict__ xhi, __half* __restrict__ xlo,
                               __half* __restrict__ wq, __half* __restrict__ wk,
                               __half* __restrict__ wv, __half* __restrict__ wo) {
    const int z = blockIdx.y;
    int i = blockIdx.x * blockDim.x + threadIdx.x;
    if (z == 0) {
        if (i >= TOK * EMB / 4) return;
        float4 v = *(const float4*)(x + i * 4);
        *(uint32_t*)(xhi + i * 4)     = packh2(v.x, v.y);
        *(uint32_t*)(xhi + i * 4 + 2) = packh2(v.z, v.w);
        *(uint32_t*)(xlo + i * 4)     = packh_lo2(v.x, v.y);
        *(uint32_t*)(xlo + i * 4 + 2) = packh_lo2(v.z, v.w);
    } else {
        if (i >= EMB * EMB / 4) return;
        const float* in = (z == 1) ? w0 : (z == 2) ? w1 : (z == 3) ? w2 : w3;
        __half* o = (z == 1) ? wq : (z == 2) ? wk : (z == 3) ? wv : wo;
        float4 v = *(const float4*)(in + i * 4);
        *(uint32_t*)(o + i * 4)     = packh2(v.x, v.y);
        *(uint32_t*)(o + i * 4 + 2) = packh2(v.z, v.w);
    }
}

// ======== mma.sync fp16 GEMM: C = (Ahi+Alo) @ W^T, 2 MMAs/output-frag, 128x128 tile ========
#define MT 128
#define NT 128
#define KT 64
#define NKTILE (EMB / KT)             // 16
#define TILE_A (128 * 128)            // 16KB (128 rows x 64 fp16)
#define TILE_B (128 * 128)            // 16KB
#define STAGE_BYTES (2 * TILE_A + TILE_B)   // 48KB
#define GEMM_SMEM (2 * STAGE_BYTES)   // 96KB -> 2 CTAs/SM

// Epilogue modes: 0 = fp32 C, 1 = fp16 hi/lo split, 2 = fp16 hi only
__device__ __forceinline__ void gemm_core(
        const __half* __restrict__ Ahi, const __half* __restrict__ Alo,
        const __half* __restrict__ B,
        float* __restrict__ C, __half* __restrict__ Chi, __half* __restrict__ Clo,
        int mode, const uint32_t smb, int rowBase, int colBase) {
    const int tid = threadIdx.x;
    const int lane = tid & 31;
    const int wid = tid >> 5;
    const int wm = wid >> 2;          // 0..1 (64 rows each)
    const int wn = wid & 3;           // 0..3 (32 cols each)

    float acc[4][4][4];
#pragma unroll
    for (int mi = 0; mi < 4; mi++)
#pragma unroll
        for (int ni = 0; ni < 4; ni++)
#pragma unroll
            for (int j = 0; j < 4; j++) acc[mi][ni][j] = 0.f;

    auto load_stage = [&](int s, int kt) {
        const int k0 = kt * KT;
        uint32_t sb = smb + s * STAGE_BYTES;
        // A hi+lo: 2 x 1024 chunks
#pragma unroll
        for (int it = 0; it < 8; it++) {
            int idx = tid + it * 256;
            int arr = idx >> 10;
            int rc  = idx & 1023;
            int row = rc >> 3;
            int ch  = rc & 7;
            uint32_t soff = sb + arr * TILE_A + row * 128 + ((ch ^ (row & 7)) * 16);
            const __half* src = arr ? Alo : Ahi;
            CP_ASYNC16(soff, src + (size_t)(rowBase + row) * EMB + k0 + ch * 8);
        }
        // B single: 1024 chunks
#pragma unroll
        for (int it = 0; it < 4; it++) {
            int idx = tid + it * 256;
            int row = idx >> 3;
            int ch  = idx & 7;
            uint32_t soff = sb + 2 * TILE_A + row * 128 + ((ch ^ (row & 7)) * 16);
            CP_ASYNC16(soff, B + (size_t)(colBase + row) * EMB + k0 + ch * 8);
        }
        CP_COMMIT();
    };

    auto compute_stage = [&](int s) {
        const uint32_t sah = smb + s * STAGE_BYTES;
        const uint32_t sal = sah + TILE_A;
        const uint32_t sbh = sah + 2 * TILE_A;
#pragma unroll
        for (int ks = 0; ks < 4; ks++) {
            uint32_t ahi[4][4], alo[4][4];
#pragma unroll
            for (int mi = 0; mi < 4; mi++) {
                int row = wm * 64 + mi * 16 + (lane & 15);
                int ch = ks * 2 + (lane >> 4);
                uint32_t off = row * 128 + ((ch ^ (row & 7)) * 16);
                LDSM_X4(ahi[mi], sah + off);
                LDSM_X4(alo[mi], sal + off);
            }
            uint32_t bf[4][2];
#pragma unroll
            for (int nip = 0; nip < 2; nip++) {
                int ni = nip * 2;
                int row = wn * 32 + (ni + (lane >> 4)) * 8 + (lane & 7);
                int ch = ks * 2 + ((lane >> 3) & 1);
                uint32_t off = row * 128 + ((ch ^ (row & 7)) * 16);
                uint32_t t4[4];
                LDSM_X4(t4, sbh + off);
                bf[ni][0] = t4[0]; bf[ni][1] = t4[1];
                bf[ni + 1][0] = t4[2]; bf[ni + 1][1] = t4[3];
            }
#pragma unroll
            for (int mi = 0; mi < 4; mi++)
#pragma unroll
                for (int ni = 0; ni < 4; ni++) {
                    MMA16816H(acc[mi][ni], ahi[mi], bf[ni]);
                    MMA16816H(acc[mi][ni], alo[mi], bf[ni]);
                }
        }
    };

    load_stage(0, 0);
    load_stage(1, 1);
    for (int t = 0; t < NKTILE; t++) {
        if (t < NKTILE - 2) CP_WAIT1(); else CP_WAIT0();
        __syncthreads();
        compute_stage(t & 1);
        __syncthreads();
        if (t + 2 < NKTILE) load_stage(t & 1, t + 2);
    }

#pragma unroll
    for (int mi = 0; mi < 4; mi++) {
#pragma unroll
        for (int ni = 0; ni < 4; ni++) {
            int row = rowBase + wm * 64 + mi * 16 + (lane >> 2);
            int col = colBase + wn * 32 + ni * 8 + (lane & 3) * 2;
            size_t o0 = (size_t)row * EMB + col;
            size_t o1 = (size_t)(row + 8) * EMB + col;
            if (mode == 0) {
                *(float2*)&C[o0] = make_float2(acc[mi][ni][0], acc[mi][ni][1]);
                *(float2*)&C[o1] = make_float2(acc[mi][ni][2], acc[mi][ni][3]);
            } else if (mode == 1) {
                *(uint32_t*)&Chi[o0] = packh2(acc[mi][ni][0], acc[mi][ni][1]);
                *(uint32_t*)&Clo[o0] = packh_lo2(acc[mi][ni][0], acc[mi][ni][1]);
                *(uint32_t*)&Chi[o1] = packh2(acc[mi][ni][2], acc[mi][ni][3]);
                *(uint32_t*)&Clo[o1] = packh_lo2(acc[mi][ni][2], acc[mi][ni][3]);
            } else {
                *(uint32_t*)&Chi[o0] = packh2(acc[mi][ni][0], acc[mi][ni][1]);
                *(uint32_t*)&Chi[o1] = packh2(acc[mi][ni][2], acc[mi][ni][3]);
            }
        }
    }
}

// Fused QKV. z=0: Q (hi/lo), z=1: K (hi only), z=2: V (hi/lo)
__global__ void __launch_bounds__(256, 2)
gemm_qkv_kernel(const __half* __restrict__ xhi, const __half* __restrict__ xlo,
                const __half* __restrict__ wq, const __half* __restrict__ wk,
                const __half* __restrict__ wv,
                __half* __restrict__ qh, __half* __restrict__ ql,
                __half* __restrict__ kh,
                __half* __restrict__ vh, __half* __restrict__ vl) {
    extern __shared__ char sm[];
    const int z = blockIdx.z;
    const __half* B = (z == 0) ? wq : (z == 1) ? wk : wv;
    __half* Ch = (z == 0) ? qh : (z == 1) ? kh : vh;
    __half* Cl = (z == 0) ? ql : (z == 1) ? nullptr : vl;
    int mode = (z == 1) ? 2 : 1;
    gemm_core(xhi, xlo, B, nullptr, Ch, Cl, mode, smem_u32(sm),
              blockIdx.y * MT, blockIdx.x * NT);
}

__global__ void __launch_bounds__(256, 2)
gemm_o_kernel(const __half* __restrict__ ahi, const __half* __restrict__ alo,
              const __half* __restrict__ wo, float* __restrict__ out) {
    extern __shared__ char sm[];
    gemm_core(ahi, alo, wo, out, nullptr, nullptr, 0, smem_u32(sm),
              blockIdx.y * MT, blockIdx.x * NT);
}

// ============ Flash attention fp16: QK = (Qh+Ql)·K (2 MMAs), PV = P·(Vh+Vl) (2 MMAs) ============
#define ATILE (128 * 128)          // 16KB
#define KVTILE (64 * 128)          // 8KB
#define KVSTAGE (3 * KVTILE)       // 24KB: K, Vh, Vl
#define Q_OFF 0
#define KV_OFF (2 * ATILE)         // 32KB
#define ATTN_SMEM (2 * ATILE + 2 * KVSTAGE)  // 80KB -> 2 CTAs/SM

__global__ void __launch_bounds__(256, 2)
attn_mma_kernel(const __half* __restrict__ Qhi, const __half* __restrict__ Qlo,
                const __half* __restrict__ Kh,
                const __half* __restrict__ Vhi, const __half* __restrict__ Vlo,
                __half* __restrict__ Ohi, __half* __restrict__ Olo) {
    extern __shared__ char sm[];
    const uint32_t smb = smem_u32(sm);

    const int tid = threadIdx.x;
    const int lane = tid & 31;
    const int wid = tid >> 5;
    const int qt = gridDim.x - 1 - blockIdx.x;
    const int h  = blockIdx.y;
    const int b  = blockIdx.z;

    const size_t base = (size_t)b * SEQ * EMB + (size_t)h * HDIM;
    const __half* qh = Qhi + base;
    const __half* ql = Qlo + base;
    const __half* kh = Kh + base;
    const __half* vh = Vhi + base;
    const __half* vl = Vlo + base;

    auto load_kv = [&](int s, int kt) {
        const __half* bases[3] = {kh, vh, vl};
#pragma unroll
        for (int it = 0; it < 6; it++) {
            int idx = tid + it * 256;      // 0..1535
            int arr = idx >> 9;            // 0..2
            int rc  = idx & 511;
            int row = rc >> 3;
            int ch  = rc & 7;
            uint32_t soff = smb + KV_OFF + s * KVSTAGE + arr * KVTILE
                          + row * 128 + ((ch ^ (row & 7)) * 16);
            CP_ASYNC16(soff, bases[arr] + (size_t)(kt * 64 + row) * EMB + ch * 8);
        }
        CP_COMMIT();
    };

    // group 0: Q tile hi+lo
#pragma unroll
    for (int it = 0; it < 8; it++) {
        int idx = tid + it * 256;
        int arr = idx >> 10;
        int rc  = idx & 1023;
        int row = rc >> 3;
        int ch  = rc & 7;
        uint32_t soff = smb + Q_OFF + arr * ATILE + row * 128 + ((ch ^ (row & 7)) * 16);
        const __half* src = (arr == 0) ? qh : ql;
        CP_ASYNC16(soff, src + (size_t)(qt * 128 + row) * EMB + ch * 8);
    }
    CP_COMMIT();

    const int ktmax = 2 * qt + 1;
    load_kv(0, 0);

    float o[8][4];
#pragma unroll
    for (int j = 0; j < 8; j++)
#pragma unroll
        for (int c = 0; c < 4; c++) o[j][c] = 0.f;
    float m0 = -1e30f, m1 = -1e30f, l0 = 0.f, l1 = 0.f;

    const float sscale = 0.125f;
    const int qrow0 = qt * 128 + wid * 16 + (lane >> 2);
    const uint32_t sqh = smb + Q_OFF;
    const uint32_t sql = smb + Q_OFF + ATILE;

    for (int kt = 0; kt <= ktmax; kt++) {
        if (kt < ktmax) { load_kv((kt + 1) & 1, kt + 1); CP_WAIT1(); }
        else           { CP_WAIT0(); }
        __syncthreads();

        bool active = (kt * 64 <= qt * 128 + wid * 16 + 15);
        if (active) {
            const int s = kt & 1;
            const uint32_t skh = smb + KV_OFF + s * KVSTAGE + 0 * KVTILE;
            const uint32_t svh = smb + KV_OFF + s * KVSTAGE + 1 * KVTILE;
            const uint32_t svl = smb + KV_OFF + s * KVSTAGE + 2 * KVTILE;

            // ---- S = (Qh + Ql) K^T ----
            float sc[8][4];
#pragma unroll
            for (int j = 0; j < 8; j++)
#pragma unroll
                for (int c = 0; c < 4; c++) sc[j][c] = 0.f;

#pragma unroll
            for (int ks = 0; ks < 4; ks++) {
                uint32_t ah[4], al[4];
                {
                    int row = wid * 16 + (lane & 15);
                    int ch = ks * 2 + (lane >> 4);
                    uint32_t off = row * 128 + ((ch ^ (row & 7)) * 16);
                    LDSM_X4(ah, sqh + off);
                    LDSM_X4(al, sql + off);
                }
#pragma unroll
                for (int jp = 0; jp < 4; jp++) {
                    int j = jp * 2;
                    int row = (j + (lane >> 4)) * 8 + (lane & 7);
                    int ch = ks * 2 + ((lane >> 3) & 1);
                    uint32_t off = row * 128 + ((ch ^ (row & 7)) * 16);
                    uint32_t bh[4];
                    LDSM_X4(bh, skh + off);
                    MMA16816H(sc[j],     ah, (&bh[0]));
                    MMA16816H(sc[j],     al, (&bh[0]));
                    MMA16816H(sc[j + 1], ah, (&bh[2]));
                    MMA16816H(sc[j + 1], al, (&bh[2]));
                }
            }

            // ---- scale + causal mask ----
            bool diag = (kt * 64 + 63 > qt * 128 + wid * 16);
#pragma unroll
            for (int j = 0; j < 8; j++) {
                int col = kt * 64 + j * 8 + (lane & 3) * 2;
#pragma unroll
                for (int c = 0; c < 4; c++) {
                    float v = sc[j][c] * sscale;
                    if (diag) {
                        int cc = col + (c & 1);
                        int rr = qrow0 + ((c >= 2) ? 8 : 0);
                        if (cc > rr) v = -1e30f;
                    }
                    sc[j][c] = v;
                }
            }

            // ---- online softmax ----
            float mt0 = -1e30f, mt1 = -1e30f;
#pragma unroll
            for (int j = 0; j < 8; j++) {
                mt0 = fmaxf(mt0, fmaxf(sc[j][0], sc[j][1]));
                mt1 = fmaxf(mt1, fmaxf(sc[j][2], sc[j][3]));
            }
            mt0 = fmaxf(mt0, __shfl_xor_sync(0xffffffffu, mt0, 1));
            mt0 = fmaxf(mt0, __shfl_xor_sync(0xffffffffu, mt0, 2));
            mt1 = fmaxf(mt1, __shfl_xor_sync(0xffffffffu, mt1, 1));
            mt1 = fmaxf(mt1, __shfl_xor_sync(0xffffffffu, mt1, 2));

            float mn0 = fmaxf(m0, mt0), mn1 = fmaxf(m1, mt1);
            float corr0 = __expf(m0 - mn0), corr1 = __expf(m1 - mn1);

            float ps0 = 0.f, ps1 = 0.f;
#pragma unroll
            for (int j = 0; j < 8; j++) {
                float p0 = __expf(sc[j][0] - mn0);
                float p1 = __expf(sc[j][1] - mn0);
                float p2 = __expf(sc[j][2] - mn1);
                float p3 = __expf(sc[j][3] - mn1);
                sc[j][0] = p0; sc[j][1] = p1; sc[j][2] = p2; sc[j][3] = p3;
                ps0 += p0 + p1; ps1 += p2 + p3;
            }
            ps0 += __shfl_xor_sync(0xffffffffu, ps0, 1);
            ps0 += __shfl_xor_sync(0xffffffffu, ps0, 2);
            ps1 += __shfl_xor_sync(0xffffffffu, ps1, 1);
            ps1 += __shfl_xor_sync(0xffffffffu, ps1, 2);

            l0 = l0 * corr0 + ps0; m0 = mn0;
            l1 = l1 * corr1 + ps1; m1 = mn1;
#pragma unroll
            for (int j = 0; j < 8; j++) {
                o[j][0] *= corr0; o[j][1] *= corr0;
                o[j][2] *= corr1; o[j][3] *= corr1;
            }

            // ---- O += P (Vh + Vl) ----
#pragma unroll
            for (int ks = 0; ks < 4; ks++) {
                uint32_t ph[4];
                ph[0] = packh2(sc[2*ks][0],   sc[2*ks][1]);
                ph[1] = packh2(sc[2*ks][2],   sc[2*ks][3]);
                ph[2] = packh2(sc[2*ks+1][0], sc[2*ks+1][1]);
                ph[3] = packh2(sc[2*ks+1][2], sc[2*ks+1][3]);
#pragma unroll
                for (int j = 0; j < 4; j++) {
                    uint32_t bh[4], bl[4];
                    int row = ks * 16 + (lane & 15);
                    int ch = j * 2 + (lane >> 4);
                    uint32_t off = row * 128 + ((ch ^ (row & 7)) * 16);
                    LDSM_X4T(bh, svh + off);
                    LDSM_X4T(bl, svl + off);
                    MMA16816H(o[2*j],     ph, (&bh[0]));
                    MMA16816H(o[2*j],     ph, (&bl[0]));
                    MMA16816H(o[2*j + 1], ph, (&bh[2]));
                    MMA16816H(o[2*j + 1], ph, (&bl[2]));
                }
            }
        }
        __syncthreads();
    }

    // ---- normalize + fp16 hi/lo store (for Wo GEMM) ----
    float inv0 = 1.f / l0, inv1 = 1.f / l1;
    const int row0 = b * SEQ + qt * 128 + wid * 16 + (lane >> 2);
#pragma unroll
    for (int j = 0; j < 8; j++) {
        float a0 = o[j][0] * inv0, a1 = o[j][1] * inv0;
        float a2 = o[j][2] * inv1, a3 = o[j][3] * inv1;
        size_t off0 = (size_t)row0 * EMB + h * HDIM + j * 8 + (lane & 3) * 2;
        size_t off1 = off0 + (size_t)8 * EMB;
        *(uint32_t*)&Ohi[off0] = packh2(a0, a1);
        *(uint32_t*)&Olo[off0] = packh_lo2(a0, a1);
        *(uint32_t*)&Ohi[off1] = packh2(a2, a3);
        *(uint32_t*)&Olo[off1] = packh_lo2(a2, a3);
    }
}

// ======================= Scratch =======================
__device__ __half g_xhi[TOK * EMB], g_xlo[TOK * EMB];
__device__ __half g_qhi[TOK * EMB], g_qlo[TOK * EMB];
__device__ __half g_kh[TOK * EMB];
__device__ __half g_vhi[TOK * EMB], g_vlo[TOK * EMB];
__device__ __half g_ahi[TOK * EMB], g_alo[TOK * EMB];
__device__ __half g_wq[EMB * EMB], g_wk[EMB * EMB], g_wv[EMB * EMB], g_wo[EMB * EMB];

extern "C" void kernel_launch(void* const* d_in, const int* in_sizes, int n_in,
                              void* d_out, int out_size) {
    const float* x  = (const float*)d_in[0];
    const float* Wq = (const float*)d_in[2];
    const float* Wk = (const float*)d_in[3];
    const float* Wv = (const float*)d_in[4];
    const float* Wo = (const float*)d_in[5];
    float* out = (float*)d_out;

    __half *xhi, *xlo, *qhi, *qlo, *kh, *vhi, *vlo, *ahi, *alo;
    __half *wq, *wk, *wv, *wo;
    cudaGetSymbolAddress((void**)&xhi, g_xhi); cudaGetSymbolAddress((void**)&xlo, g_xlo);
    cudaGetSymbolAddress((void**)&qhi, g_qhi); cudaGetSymbolAddress((void**)&qlo, g_qlo);
    cudaGetSymbolAddress((void**)&kh, g_kh);
    cudaGetSymbolAddress((void**)&vhi, g_vhi); cudaGetSymbolAddress((void**)&vlo, g_vlo);
    cudaGetSymbolAddress((void**)&ahi, g_ahi); cudaGetSymbolAddress((void**)&alo, g_alo);
    cudaGetSymbolAddress((void**)&wq, g_wq);   cudaGetSymbolAddress((void**)&wk, g_wk);
    cudaGetSymbolAddress((void**)&wv, g_wv);   cudaGetSymbolAddress((void**)&wo, g_wo);

    static bool attrs_set = false;
    if (!attrs_set) {
        cudaFuncSetAttribute(gemm_qkv_kernel,
                             cudaFuncAttributeMaxDynamicSharedMemorySize, GEMM_SMEM);
        cudaFuncSetAttribute(gemm_o_kernel,
                             cudaFuncAttributeMaxDynamicSharedMemorySize, GEMM_SMEM);
        cudaFuncSetAttribute(attn_mma_kernel,
                             cudaFuncAttributeMaxDynamicSharedMemorySize, ATTN_SMEM);
        attrs_set = true;
    }

    const int XB = (TOK * EMB / 4 + 255) / 256;
    dim3 cvtGrid(XB, 5);
    cvt_all_kernel<<<cvtGrid, 256>>>(x, Wq, Wk, Wv, Wo,
                                     xhi, xlo, wq, wk, wv, wo);

    dim3 qkvGrid(EMB / NT, TOK / MT, 3);   // (8, 32, 3)
    gemm_qkv_kernel<<<qkvGrid, 256, GEMM_SMEM>>>(xhi, xlo, wq, wk, wv,
                                                 qhi, qlo, kh, vhi, vlo);

    dim3 attnGrid(SEQ / 128, HEADS, BATCH);   // (16, 16, 2)
    attn_mma_kernel<<<attnGrid, 256, ATTN_SMEM>>>(qhi, qlo, kh, vhi, vlo, ahi, alo);

    dim3 oGrid(EMB / NT, TOK / MT);   // (8, 32)
    gemm_o_kernel<<<oGrid, 256, GEMM_SMEM>>>(ahi, alo, wo, out);
}

// round 11
// speedup vs baseline: 19.7298x; 1.2029x over previous
#include <cuda_runtime.h>
#include <cuda_bf16.h>
#include <cuda_fp16.h>
#include <cstdint>
#include <math.h>

#define BATCH 2
#define SEQ   2048
#define EMB   1024
#define HEADS 16
#define HDIM  64
#define TOK   (BATCH * SEQ)   // 4096

// ======================= PTX helpers (sm_80-era ISA only) =======================
__device__ __forceinline__ uint32_t smem_u32(const void* p) {
    uint32_t a;
    asm("{ .reg .u64 t; cvta.to.shared.u64 t, %1; cvt.u32.u64 %0, t; }"
        : "=r"(a) : "l"(p));
    return a;
}

#define LDSM_X4(r, a) \
    asm volatile("ldmatrix.sync.aligned.m8n8.x4.shared.b16 {%0,%1,%2,%3}, [%4];" \
                 : "=r"((r)[0]), "=r"((r)[1]), "=r"((r)[2]), "=r"((r)[3]) : "r"(a))

#define LDSM_X4T(r, a) \
    asm volatile("ldmatrix.sync.aligned.m8n8.x4.trans.shared.b16 {%0,%1,%2,%3}, [%4];" \
                 : "=r"((r)[0]), "=r"((r)[1]), "=r"((r)[2]), "=r"((r)[3]) : "r"(a))

#define MMA16816H(d, a, b) \
    asm volatile("mma.sync.aligned.m16n8k16.row.col.f32.f16.f16.f32 " \
                 "{%0,%1,%2,%3}, {%4,%5,%6,%7}, {%8,%9}, {%0,%1,%2,%3};" \
                 : "+f"((d)[0]), "+f"((d)[1]), "+f"((d)[2]), "+f"((d)[3]) \
                 : "r"((a)[0]), "r"((a)[1]), "r"((a)[2]), "r"((a)[3]), \
                   "r"((b)[0]), "r"((b)[1]))

#define CP_ASYNC16(saddr, gaddr) \
    asm volatile("cp.async.cg.shared.global [%0], [%1], 16;" :: "r"(saddr), "l"(gaddr))
#define CP_COMMIT() asm volatile("cp.async.commit_group;" ::: "memory")
#define CP_WAIT1() asm volatile("cp.async.wait_group 1;" ::: "memory")
#define CP_WAIT0() asm volatile("cp.async.wait_group 0;" ::: "memory")

__device__ __forceinline__ uint32_t packh2(float x, float y) {
    __half2 t = __floats2half2_rn(x, y);
    return *(uint32_t*)&t;
}
__device__ __forceinline__ uint32_t packh_lo2(float x, float y) {
    __half hx = __float2half_rn(x), hy = __float2half_rn(y);
    __half2 t = __halves2half2(__float2half_rn(x - __half2float(hx)),
                               __float2half_rn(y - __half2float(hy)));
    return *(uint32_t*)&t;
}

// ============ fused cvt: x -> single fp16 (y=0); weights -> single fp16 (y=1..4) ============
__global__ void cvt_all_kernel(const float* __restrict__ x,
                               const float* __restrict__ w0, const float* __restrict__ w1,
                               const float* __restrict__ w2, const float* __restrict__ w3,
                               __half* __restrict__ xh,
                               __half* __restrict__ wq, __half* __restrict__ wk,
                               __half* __restrict__ wv, __half* __restrict__ wo) {
    const int z = blockIdx.y;
    int i = blockIdx.x * blockDim.x + threadIdx.x;
    if (z == 0) {
        if (i >= TOK * EMB / 4) return;
        float4 v = *(const float4*)(x + i * 4);
        *(uint32_t*)(xh + i * 4)     = packh2(v.x, v.y);
        *(uint32_t*)(xh + i * 4 + 2) = packh2(v.z, v.w);
    } else {
        if (i >= EMB * EMB / 4) return;
        const float* in = (z == 1) ? w0 : (z == 2) ? w1 : (z == 3) ? w2 : w3;
        __half* o = (z == 1) ? wq : (z == 2) ? wk : (z == 3) ? wv : wo;
        float4 v = *(const float4*)(in + i * 4);
        *(uint32_t*)(o + i * 4)     = packh2(v.x, v.y);
        *(uint32_t*)(o + i * 4 + 2) = packh2(v.z, v.w);
    }
}

// ======== mma.sync fp16 GEMM, templated on #A-terms. 128x128 tile, 2 CTAs/SM ========
#define MT 128
#define NT 128
#define KT 64
#define NKTILE (EMB / KT)             // 16
#define TILE_H (128 * 128)            // 16KB (128 rows x 64 fp16)

// stage bytes = (NA + 1) * TILE_H
// Epilogue modes: 0 = fp32 C, 1 = fp16 hi/lo split, 2 = fp16 hi only
template <int NA>
__device__ __forceinline__ void gemm_core(
        const __half* __restrict__ Ahi, const __half* __restrict__ Alo,
        const __half* __restrict__ B,
        float* __restrict__ C, __half* __restrict__ Chi, __half* __restrict__ Clo,
        int mode, const uint32_t smb, int rowBase, int colBase) {
    constexpr uint32_t STAGE = (NA + 1) * TILE_H;
    const int tid = threadIdx.x;
    const int lane = tid & 31;
    const int wid = tid >> 5;
    const int wm = wid >> 2;          // 0..1 (64 rows each)
    const int wn = wid & 3;           // 0..3 (32 cols each)

    float acc[4][4][4];
#pragma unroll
    for (int mi = 0; mi < 4; mi++)
#pragma unroll
        for (int ni = 0; ni < 4; ni++)
#pragma unroll
            for (int j = 0; j < 4; j++) acc[mi][ni][j] = 0.f;

    auto load_stage = [&](int s, int kt) {
        const int k0 = kt * KT;
        uint32_t sb = smb + s * STAGE;
        // A: NA x 1024 chunks
#pragma unroll
        for (int it = 0; it < 4 * NA; it++) {
            int idx = tid + it * 256;
            int arr = idx >> 10;
            int rc  = idx & 1023;
            int row = rc >> 3;
            int ch  = rc & 7;
            uint32_t soff = sb + arr * TILE_H + row * 128 + ((ch ^ (row & 7)) * 16);
            const __half* src = arr ? Alo : Ahi;
            CP_ASYNC16(soff, src + (size_t)(rowBase + row) * EMB + k0 + ch * 8);
        }
        // B single: 1024 chunks
#pragma unroll
        for (int it = 0; it < 4; it++) {
            int idx = tid + it * 256;
            int row = idx >> 3;
            int ch  = idx & 7;
            uint32_t soff = sb + NA * TILE_H + row * 128 + ((ch ^ (row & 7)) * 16);
            CP_ASYNC16(soff, B + (size_t)(colBase + row) * EMB + k0 + ch * 8);
        }
        CP_COMMIT();
    };

    auto compute_stage = [&](int s) {
        const uint32_t sah = smb + s * STAGE;
        const uint32_t sal = sah + TILE_H;
        const uint32_t sbh = sah + NA * TILE_H;
#pragma unroll
        for (int ks = 0; ks < 4; ks++) {
            uint32_t ahi[4][4], alo[4][4];
#pragma unroll
            for (int mi = 0; mi < 4; mi++) {
                int row = wm * 64 + mi * 16 + (lane & 15);
                int ch = ks * 2 + (lane >> 4);
                uint32_t off = row * 128 + ((ch ^ (row & 7)) * 16);
                LDSM_X4(ahi[mi], sah + off);
                if (NA == 2) LDSM_X4(alo[mi], sal + off);
            }
            uint32_t bf[4][2];
#pragma unroll
            for (int nip = 0; nip < 2; nip++) {
                int ni = nip * 2;
                int row = wn * 32 + (ni + (lane >> 4)) * 8 + (lane & 7);
                int ch = ks * 2 + ((lane >> 3) & 1);
                uint32_t off = row * 128 + ((ch ^ (row & 7)) * 16);
                uint32_t t4[4];
                LDSM_X4(t4, sbh + off);
                bf[ni][0] = t4[0]; bf[ni][1] = t4[1];
                bf[ni + 1][0] = t4[2]; bf[ni + 1][1] = t4[3];
            }
#pragma unroll
            for (int mi = 0; mi < 4; mi++)
#pragma unroll
                for (int ni = 0; ni < 4; ni++) {
                    MMA16816H(acc[mi][ni], ahi[mi], bf[ni]);
                    if (NA == 2) MMA16816H(acc[mi][ni], alo[mi], bf[ni]);
                }
        }
    };

    load_stage(0, 0);
    load_stage(1, 1);
    for (int t = 0; t < NKTILE; t++) {
        if (t < NKTILE - 2) CP_WAIT1(); else CP_WAIT0();
        __syncthreads();
        compute_stage(t & 1);
        __syncthreads();
        if (t + 2 < NKTILE) load_stage(t & 1, t + 2);
    }

#pragma unroll
    for (int mi = 0; mi < 4; mi++) {
#pragma unroll
        for (int ni = 0; ni < 4; ni++) {
            int row = rowBase + wm * 64 + mi * 16 + (lane >> 2);
            int col = colBase + wn * 32 + ni * 8 + (lane & 3) * 2;
            size_t o0 = (size_t)row * EMB + col;
            size_t o1 = (size_t)(row + 8) * EMB + col;
            if (mode == 0) {
                *(float2*)&C[o0] = make_float2(acc[mi][ni][0], acc[mi][ni][1]);
                *(float2*)&C[o1] = make_float2(acc[mi][ni][2], acc[mi][ni][3]);
            } else if (mode == 1) {
                *(uint32_t*)&Chi[o0] = packh2(acc[mi][ni][0], acc[mi][ni][1]);
                *(uint32_t*)&Clo[o0] = packh_lo2(acc[mi][ni][0], acc[mi][ni][1]);
                *(uint32_t*)&Chi[o1] = packh2(acc[mi][ni][2], acc[mi][ni][3]);
                *(uint32_t*)&Clo[o1] = packh_lo2(acc[mi][ni][2], acc[mi][ni][3]);
            } else {
                *(uint32_t*)&Chi[o0] = packh2(acc[mi][ni][0], acc[mi][ni][1]);
                *(uint32_t*)&Chi[o1] = packh2(acc[mi][ni][2], acc[mi][ni][3]);
            }
        }
    }
}

#define QKV_SMEM (2 * 2 * TILE_H)     // NA=1: 2 stages x 32KB = 64KB
#define WO_SMEM  (2 * 3 * TILE_H)     // NA=2: 2 stages x 48KB = 96KB

// Fused QKV (x single fp16). z=0: Q (hi/lo out), z=1: K (hi only), z=2: V (hi/lo)
__global__ void __launch_bounds__(256, 2)
gemm_qkv_kernel(const __half* __restrict__ xh,
                const __half* __restrict__ wq, const __half* __restrict__ wk,
                const __half* __restrict__ wv,
                __half* __restrict__ qh, __half* __restrict__ ql,
                __half* __restrict__ kh,
                __half* __restrict__ vh, __half* __restrict__ vl) {
    extern __shared__ char sm[];
    const int z = blockIdx.z;
    const __half* B = (z == 0) ? wq : (z == 1) ? wk : wv;
    __half* Ch = (z == 0) ? qh : (z == 1) ? kh : vh;
    __half* Cl = (z == 0) ? ql : (z == 1) ? nullptr : vl;
    int mode = (z == 1) ? 2 : 1;
    gemm_core<1>(xh, nullptr, B, nullptr, Ch, Cl, mode, smem_u32(sm),
                 blockIdx.y * MT, blockIdx.x * NT);
}

__global__ void __launch_bounds__(256, 2)
gemm_o_kernel(const __half* __restrict__ ahi, const __half* __restrict__ alo,
              const __half* __restrict__ wo, float* __restrict__ out) {
    extern __shared__ char sm[];
    gemm_core<2>(ahi, alo, wo, out, nullptr, nullptr, 0, smem_u32(sm),
                 blockIdx.y * MT, blockIdx.x * NT);
}

// ============ Flash attention fp16: QK = (Qh+Ql)·K (2 MMAs), PV = P·(Vh+Vl) (2 MMAs) ============
#define ATILE (128 * 128)          // 16KB
#define KVTILE (64 * 128)          // 8KB
#define KVSTAGE (3 * KVTILE)       // 24KB: K, Vh, Vl
#define Q_OFF 0
#define KV_OFF (2 * ATILE)         // 32KB
#define ATTN_SMEM (2 * ATILE + 2 * KVSTAGE)  // 80KB -> 2 CTAs/SM

__global__ void __launch_bounds__(256, 2)
attn_mma_kernel(const __half* __restrict__ Qhi, const __half* __restrict__ Qlo,
                const __half* __restrict__ Kh,
                const __half* __restrict__ Vhi, const __half* __restrict__ Vlo,
                __half* __restrict__ Ohi, __half* __restrict__ Olo) {
    extern __shared__ char sm[];
    const uint32_t smb = smem_u32(sm);

    const int tid = threadIdx.x;
    const int lane = tid & 31;
    const int wid = tid >> 5;
    const int qt = gridDim.x - 1 - blockIdx.x;
    const int h  = blockIdx.y;
    const int b  = blockIdx.z;

    const size_t base = (size_t)b * SEQ * EMB + (size_t)h * HDIM;
    const __half* qh = Qhi + base;
    const __half* ql = Qlo + base;
    const __half* kh = Kh + base;
    const __half* vh = Vhi + base;
    const __half* vl = Vlo + base;

    auto load_kv = [&](int s, int kt) {
        const __half* bases[3] = {kh, vh, vl};
#pragma unroll
        for (int it = 0; it < 6; it++) {
            int idx = tid + it * 256;      // 0..1535
            int arr = idx >> 9;            // 0..2
            int rc  = idx & 511;
            int row = rc >> 3;
            int ch  = rc & 7;
            uint32_t soff = smb + KV_OFF + s * KVSTAGE + arr * KVTILE
                          + row * 128 + ((ch ^ (row & 7)) * 16);
            CP_ASYNC16(soff, bases[arr] + (size_t)(kt * 64 + row) * EMB + ch * 8);
        }
        CP_COMMIT();
    };

    // group 0: Q tile hi+lo
#pragma unroll
    for (int it = 0; it < 8; it++) {
        int idx = tid + it * 256;
        int arr = idx >> 10;
        int rc  = idx & 1023;
        int row = rc >> 3;
        int ch  = rc & 7;
        uint32_t soff = smb + Q_OFF + arr * ATILE + row * 128 + ((ch ^ (row & 7)) * 16);
        const __half* src = (arr == 0) ? qh : ql;
        CP_ASYNC16(soff, src + (size_t)(qt * 128 + row) * EMB + ch * 8);
    }
    CP_COMMIT();

    const int ktmax = 2 * qt + 1;
    load_kv(0, 0);

    float o[8][4];
#pragma unroll
    for (int j = 0; j < 8; j++)
#pragma unroll
        for (int c = 0; c < 4; c++) o[j][c] = 0.f;
    float m0 = -1e30f, m1 = -1e30f, l0 = 0.f, l1 = 0.f;

    const float sscale = 0.125f;
    const int qrow0 = qt * 128 + wid * 16 + (lane >> 2);
    const uint32_t sqh = smb + Q_OFF;
    const uint32_t sql = smb + Q_OFF + ATILE;

    for (int kt = 0; kt <= ktmax; kt++) {
        if (kt < ktmax) { load_kv((kt + 1) & 1, kt + 1); CP_WAIT1(); }
        else           { CP_WAIT0(); }
        __syncthreads();

        bool active = (kt * 64 <= qt * 128 + wid * 16 + 15);
        if (active) {
            const int s = kt & 1;
            const uint32_t skh = smb + KV_OFF + s * KVSTAGE + 0 * KVTILE;
            const uint32_t svh = smb + KV_OFF + s * KVSTAGE + 1 * KVTILE;
            const uint32_t svl = smb + KV_OFF + s * KVSTAGE + 2 * KVTILE;

            // ---- S = (Qh + Ql) K^T ----
            float sc[8][4];
#pragma unroll
            for (int j = 0; j < 8; j++)
#pragma unroll
                for (int c = 0; c < 4; c++) sc[j][c] = 0.f;

#pragma unroll
            for (int ks = 0; ks < 4; ks++) {
                uint32_t ah[4], al[4];
                {
                    int row = wid * 16 + (lane & 15);
                    int ch = ks * 2 + (lane >> 4);
                    uint32_t off = row * 128 + ((ch ^ (row & 7)) * 16);
                    LDSM_X4(ah, sqh + off);
                    LDSM_X4(al, sql + off);
                }
#pragma unroll
                for (int jp = 0; jp < 4; jp++) {
                    int j = jp * 2;
                    int row = (j + (lane >> 4)) * 8 + (lane & 7);
                    int ch = ks * 2 + ((lane >> 3) & 1);
                    uint32_t off = row * 128 + ((ch ^ (row & 7)) * 16);
                    uint32_t bh[4];
                    LDSM_X4(bh, skh + off);
                    MMA16816H(sc[j],     ah, (&bh[0]));
                    MMA16816H(sc[j],     al, (&bh[0]));
                    MMA16816H(sc[j + 1], ah, (&bh[2]));
                    MMA16816H(sc[j + 1], al, (&bh[2]));
                }
            }

            // ---- scale + causal mask ----
            bool diag = (kt * 64 + 63 > qt * 128 + wid * 16);
#pragma unroll
            for (int j = 0; j < 8; j++) {
                int col = kt * 64 + j * 8 + (lane & 3) * 2;
#pragma unroll
                for (int c = 0; c < 4; c++) {
                    float v = sc[j][c] * sscale;
                    if (diag) {
                        int cc = col + (c & 1);
                        int rr = qrow0 + ((c >= 2) ? 8 : 0);
                        if (cc > rr) v = -1e30f;
                    }
                    sc[j][c] = v;
                }
            }

            // ---- online softmax ----
            float mt0 = -1e30f, mt1 = -1e30f;
#pragma unroll
            for (int j = 0; j < 8; j++) {
                mt0 = fmaxf(mt0, fmaxf(sc[j][0], sc[j][1]));
                mt1 = fmaxf(mt1, fmaxf(sc[j][2], sc[j][3]));
            }
            mt0 = fmaxf(mt0, __shfl_xor_sync(0xffffffffu, mt0, 1));
            mt0 = fmaxf(mt0, __shfl_xor_sync(0xffffffffu, mt0, 2));
            mt1 = fmaxf(mt1, __shfl_xor_sync(0xffffffffu, mt1, 1));
            mt1 = fmaxf(mt1, __shfl_xor_sync(0xffffffffu, mt1, 2));

            float mn0 = fmaxf(m0, mt0), mn1 = fmaxf(m1, mt1);
            float corr0 = __expf(m0 - mn0), corr1 = __expf(m1 - mn1);

            float ps0 = 0.f, ps1 = 0.f;
#pragma unroll
            for (int j = 0; j < 8; j++) {
                float p0 = __expf(sc[j][0] - mn0);
                float p1 = __expf(sc[j][1] - mn0);
                float p2 = __expf(sc[j][2] - mn1);
                float p3 = __expf(sc[j][3] - mn1);
                sc[j][0] = p0; sc[j][1] = p1; sc[j][2] = p2; sc[j][3] = p3;
                ps0 += p0 + p1; ps1 += p2 + p3;
            }
            ps0 += __shfl_xor_sync(0xffffffffu, ps0, 1);
            ps0 += __shfl_xor_sync(0xffffffffu, ps0, 2);
            ps1 += __shfl_xor_sync(0xffffffffu, ps1, 1);
            ps1 += __shfl_xor_sync(0xffffffffu, ps1, 2);

            l0 = l0 * corr0 + ps0; m0 = mn0;
            l1 = l1 * corr1 + ps1; m1 = mn1;
#pragma unroll
            for (int j = 0; j < 8; j++) {
                o[j][0] *= corr0; o[j][1] *= corr0;
                o[j][2] *= corr1; o[j][3] *= corr1;
            }

            // ---- O += P (Vh + Vl) ----
#pragma unroll
            for (int ks = 0; ks < 4; ks++) {
                uint32_t ph[4];
                ph[0] = packh2(sc[2*ks][0],   sc[2*ks][1]);
                ph[1] = packh2(sc[2*ks][2],   sc[2*ks][3]);
                ph[2] = packh2(sc[2*ks+1][0], sc[2*ks+1][1]);
                ph[3] = packh2(sc[2*ks+1][2], sc[2*ks+1][3]);
#pragma unroll
                for (int j = 0; j < 4; j++) {
                    uint32_t bh[4], bl[4];
                    int row = ks * 16 + (lane & 15);
                    int ch = j * 2 + (lane >> 4);
                    uint32_t off = row * 128 + ((ch ^ (row & 7)) * 16);
                    LDSM_X4T(bh, svh + off);
                    LDSM_X4T(bl, svl + off);
                    MMA16816H(o[2*j],     ph, (&bh[0]));
                    MMA16816H(o[2*j],     ph, (&bl[0]));
                    MMA16816H(o[2*j + 1], ph, (&bh[2]));
                    MMA16816H(o[2*j + 1], ph, (&bl[2]));
                }
            }
        }
        __syncthreads();
    }

    // ---- normalize + fp16 hi/lo store (for Wo GEMM) ----
    float inv0 = 1.f / l0, inv1 = 1.f / l1;
    const int row0 = b * SEQ + qt * 128 + wid * 16 + (lane >> 2);
#pragma unroll
    for (int j = 0; j < 8; j++) {
        float a0 = o[j][0] * inv0, a1 = o[j][1] * inv0;
        float a2 = o[j][2] * inv1, a3 = o[j][3] * inv1;
        size_t off0 = (size_t)row0 * EMB + h * HDIM + j * 8 + (lane & 3) * 2;
        size_t off1 = off0 + (size_t)8 * EMB;
        *(uint32_t*)&Ohi[off0] = packh2(a0, a1);
        *(uint32_t*)&Olo[off0] = packh_lo2(a0, a1);
        *(uint32_t*)&Ohi[off1] = packh2(a2, a3);
        *(uint32_t*)&Olo[off1] = packh_lo2(a2, a3);
    }
}

// ======================= Scratch =======================
__device__ __half g_xh[TOK * EMB];
__device__ __half g_qhi[TOK * EMB], g_qlo[TOK * EMB];
__device__ __half g_kh[TOK * EMB];
__device__ __half g_vhi[TOK * EMB], g_vlo[TOK * EMB];
__device__ __half g_ahi[TOK * EMB], g_alo[TOK * EMB];
__device__ __half g_wq[EMB * EMB], g_wk[EMB * EMB], g_wv[EMB * EMB], g_wo[EMB * EMB];

extern "C" void kernel_launch(void* const* d_in, const int* in_sizes, int n_in,
                              void* d_out, int out_size) {
    const float* x  = (const float*)d_in[0];
    const float* Wq = (const float*)d_in[2];
    const float* Wk = (const float*)d_in[3];
    const float* Wv = (const float*)d_in[4];
    const float* Wo = (const float*)d_in[5];
    float* out = (float*)d_out;

    __half *xh, *qhi, *qlo, *kh, *vhi, *vlo, *ahi, *alo;
    __half *wq, *wk, *wv, *wo;
    cudaGetSymbolAddress((void**)&xh, g_xh);
    cudaGetSymbolAddress((void**)&qhi, g_qhi); cudaGetSymbolAddress((void**)&qlo, g_qlo);
    cudaGetSymbolAddress((void**)&kh, g_kh);
    cudaGetSymbolAddress((void**)&vhi, g_vhi); cudaGetSymbolAddress((void**)&vlo, g_vlo);
    cudaGetSymbolAddress((void**)&ahi, g_ahi); cudaGetSymbolAddress((void**)&alo, g_alo);
    cudaGetSymbolAddress((void**)&wq, g_wq);   cudaGetSymbolAddress((void**)&wk, g_wk);
    cudaGetSymbolAddress((void**)&wv, g_wv);   cudaGetSymbolAddress((void**)&wo, g_wo);

    static bool attrs_set = false;
    if (!attrs_set) {
        cudaFuncSetAttribute(gemm_qkv_kernel,
                             cudaFuncAttributeMaxDynamicSharedMemorySize, QKV_SMEM);
        cudaFuncSetAttribute(gemm_o_kernel,
                             cudaFuncAttributeMaxDynamicSharedMemorySize, WO_SMEM);
        cudaFuncSetAttribute(attn_mma_kernel,
                             cudaFuncAttributeMaxDynamicSharedMemorySize, ATTN_SMEM);
        attrs_set = true;
    }

    const int XB = (TOK * EMB / 4 + 255) / 256;
    dim3 cvtGrid(XB, 5);
    cvt_all_kernel<<<cvtGrid, 256>>>(x, Wq, Wk, Wv, Wo, xh, wq, wk, wv, wo);

    dim3 qkvGrid(EMB / NT, TOK / MT, 3);   // (8, 32, 3)
    gemm_qkv_kernel<<<qkvGrid, 256, QKV_SMEM>>>(xh, wq, wk, wv,
                                                qhi, qlo, kh, vhi, vlo);

    dim3 attnGrid(SEQ / 128, HEADS, BATCH);   // (16, 16, 2)
    attn_mma_kernel<<<attnGrid, 256, ATTN_SMEM>>>(qhi, qlo, kh, vhi, vlo, ahi, alo);

    dim3 oGrid(EMB / NT, TOK / MT);   // (8, 32)
    gemm_o_kernel<<<oGrid, 256, WO_SMEM>>>(ahi, alo, wo, out);
}

// round 12
// speedup vs baseline: 26.6048x; 1.3485x over previous
#include <cuda_runtime.h>
#include <cuda_bf16.h>
#include <cuda_fp16.h>
#include <cstdint>
#include <math.h>

#define BATCH 2
#define SEQ   2048
#define EMB   1024
#define HEADS 16
#define HDIM  64
#define TOK   (BATCH * SEQ)   // 4096

// ======================= PTX helpers (sm_80-era ISA only) =======================
__device__ __forceinline__ uint32_t smem_u32(const void* p) {
    uint32_t a;
    asm("{ .reg .u64 t; cvta.to.shared.u64 t, %1; cvt.u32.u64 %0, t; }"
        : "=r"(a) : "l"(p));
    return a;
}

#define LDSM_X4(r, a) \
    asm volatile("ldmatrix.sync.aligned.m8n8.x4.shared.b16 {%0,%1,%2,%3}, [%4];" \
                 : "=r"((r)[0]), "=r"((r)[1]), "=r"((r)[2]), "=r"((r)[3]) : "r"(a))

#define LDSM_X4T(r, a) \
    asm volatile("ldmatrix.sync.aligned.m8n8.x4.trans.shared.b16 {%0,%1,%2,%3}, [%4];" \
                 : "=r"((r)[0]), "=r"((r)[1]), "=r"((r)[2]), "=r"((r)[3]) : "r"(a))

#define MMA16816H(d, a, b) \
    asm volatile("mma.sync.aligned.m16n8k16.row.col.f32.f16.f16.f32 " \
                 "{%0,%1,%2,%3}, {%4,%5,%6,%7}, {%8,%9}, {%0,%1,%2,%3};" \
                 : "+f"((d)[0]), "+f"((d)[1]), "+f"((d)[2]), "+f"((d)[3]) \
                 : "r"((a)[0]), "r"((a)[1]), "r"((a)[2]), "r"((a)[3]), \
                   "r"((b)[0]), "r"((b)[1]))

#define CP_ASYNC16(saddr, gaddr) \
    asm volatile("cp.async.cg.shared.global [%0], [%1], 16;" :: "r"(saddr), "l"(gaddr))
#define CP_COMMIT() asm volatile("cp.async.commit_group;" ::: "memory")
#define CP_WAIT1() asm volatile("cp.async.wait_group 1;" ::: "memory")
#define CP_WAIT0() asm volatile("cp.async.wait_group 0;" ::: "memory")

__device__ __forceinline__ uint32_t packh2(float x, float y) {
    __half2 t = __floats2half2_rn(x, y);
    return *(uint32_t*)&t;
}

// ============ fused cvt: x + 4 weights -> single fp16 ============
__global__ void cvt_all_kernel(const float* __restrict__ x,
                               const float* __restrict__ w0, const float* __restrict__ w1,
                               const float* __restrict__ w2, const float* __restrict__ w3,
                               __half* __restrict__ xh,
                               __half* __restrict__ wq, __half* __restrict__ wk,
                               __half* __restrict__ wv, __half* __restrict__ wo) {
    const int z = blockIdx.y;
    int i = blockIdx.x * blockDim.x + threadIdx.x;
    const float* in;
    __half* o;
    int n4;
    if (z == 0)      { in = x;  o = xh; n4 = TOK * EMB / 4; }
    else if (z == 1) { in = w0; o = wq; n4 = EMB * EMB / 4; }
    else if (z == 2) { in = w1; o = wk; n4 = EMB * EMB / 4; }
    else if (z == 3) { in = w2; o = wv; n4 = EMB * EMB / 4; }
    else             { in = w3; o = wo; n4 = EMB * EMB / 4; }
    if (i >= n4) return;
    float4 v = *(const float4*)(in + i * 4);
    *(uint32_t*)(o + i * 4)     = packh2(v.x, v.y);
    *(uint32_t*)(o + i * 4 + 2) = packh2(v.z, v.w);
}

// ======== mma.sync fp16 GEMM: single-term A and B. 128x128 tile, 2 CTAs/SM ========
#define MT 128
#define NT 128
#define KT 64
#define NKTILE (EMB / KT)             // 16
#define TILE_H (128 * 128)            // 16KB (128 rows x 64 fp16)
#define GEMM_STAGE (2 * TILE_H)       // 32KB (A + B)
#define GEMM_SMEM (2 * GEMM_STAGE)    // 64KB

// Epilogue modes: 0 = fp32 C, 2 = fp16
__device__ __forceinline__ void gemm_core(
        const __half* __restrict__ A, const __half* __restrict__ B,
        float* __restrict__ C, __half* __restrict__ Ch,
        int mode, const uint32_t smb, int rowBase, int colBase) {
    const int tid = threadIdx.x;
    const int lane = tid & 31;
    const int wid = tid >> 5;
    const int wm = wid >> 2;          // 0..1 (64 rows each)
    const int wn = wid & 3;           // 0..3 (32 cols each)

    float acc[4][4][4];
#pragma unroll
    for (int mi = 0; mi < 4; mi++)
#pragma unroll
        for (int ni = 0; ni < 4; ni++)
#pragma unroll
            for (int j = 0; j < 4; j++) acc[mi][ni][j] = 0.f;

    auto load_stage = [&](int s, int kt) {
        const int k0 = kt * KT;
        uint32_t sb = smb + s * GEMM_STAGE;
#pragma unroll
        for (int it = 0; it < 8; it++) {
            int idx = tid + it * 256;      // 0..2047
            int arr = idx >> 10;           // 0: A, 1: B
            int rc  = idx & 1023;
            int row = rc >> 3;
            int ch  = rc & 7;
            uint32_t soff = sb + arr * TILE_H + row * 128 + ((ch ^ (row & 7)) * 16);
            const __half* src = arr ? B : A;
            int rb = arr ? colBase : rowBase;
            CP_ASYNC16(soff, src + (size_t)(rb + row) * EMB + k0 + ch * 8);
        }
        CP_COMMIT();
    };

    auto compute_stage = [&](int s) {
        const uint32_t sa = smb + s * GEMM_STAGE;
        const uint32_t sb2 = sa + TILE_H;
#pragma unroll
        for (int ks = 0; ks < 4; ks++) {
            uint32_t af[4][4];
#pragma unroll
            for (int mi = 0; mi < 4; mi++) {
                int row = wm * 64 + mi * 16 + (lane & 15);
                int ch = ks * 2 + (lane >> 4);
                uint32_t off = row * 128 + ((ch ^ (row & 7)) * 16);
                LDSM_X4(af[mi], sa + off);
            }
            uint32_t bf[4][2];
#pragma unroll
            for (int nip = 0; nip < 2; nip++) {
                int ni = nip * 2;
                int row = wn * 32 + (ni + (lane >> 4)) * 8 + (lane & 7);
                int ch = ks * 2 + ((lane >> 3) & 1);
                uint32_t off = row * 128 + ((ch ^ (row & 7)) * 16);
                uint32_t t4[4];
                LDSM_X4(t4, sb2 + off);
                bf[ni][0] = t4[0]; bf[ni][1] = t4[1];
                bf[ni + 1][0] = t4[2]; bf[ni + 1][1] = t4[3];
            }
#pragma unroll
            for (int mi = 0; mi < 4; mi++)
#pragma unroll
                for (int ni = 0; ni < 4; ni++)
                    MMA16816H(acc[mi][ni], af[mi], bf[ni]);
        }
    };

    load_stage(0, 0);
    load_stage(1, 1);
    for (int t = 0; t < NKTILE; t++) {
        if (t < NKTILE - 2) CP_WAIT1(); else CP_WAIT0();
        __syncthreads();
        compute_stage(t & 1);
        __syncthreads();
        if (t + 2 < NKTILE) load_stage(t & 1, t + 2);
    }

#pragma unroll
    for (int mi = 0; mi < 4; mi++) {
#pragma unroll
        for (int ni = 0; ni < 4; ni++) {
            int row = rowBase + wm * 64 + mi * 16 + (lane >> 2);
            int col = colBase + wn * 32 + ni * 8 + (lane & 3) * 2;
            size_t o0 = (size_t)row * EMB + col;
            size_t o1 = (size_t)(row + 8) * EMB + col;
            if (mode == 0) {
                *(float2*)&C[o0] = make_float2(acc[mi][ni][0], acc[mi][ni][1]);
                *(float2*)&C[o1] = make_float2(acc[mi][ni][2], acc[mi][ni][3]);
            } else {
                *(uint32_t*)&Ch[o0] = packh2(acc[mi][ni][0], acc[mi][ni][1]);
                *(uint32_t*)&Ch[o1] = packh2(acc[mi][ni][2], acc[mi][ni][3]);
            }
        }
    }
}

// Fused QKV (all single fp16 in and out)
__global__ void __launch_bounds__(256, 2)
gemm_qkv_kernel(const __half* __restrict__ xh,
                const __half* __restrict__ wq, const __half* __restrict__ wk,
                const __half* __restrict__ wv,
                __half* __restrict__ qh, __half* __restrict__ kh,
                __half* __restrict__ vh) {
    extern __shared__ char sm[];
    const int z = blockIdx.z;
    const __half* B = (z == 0) ? wq : (z == 1) ? wk : wv;
    __half* Ch = (z == 0) ? qh : (z == 1) ? kh : vh;
    gemm_core(xh, B, nullptr, Ch, 2, smem_u32(sm),
              blockIdx.y * MT, blockIdx.x * NT);
}

__global__ void __launch_bounds__(256, 2)
gemm_o_kernel(const __half* __restrict__ ah, const __half* __restrict__ wo,
              float* __restrict__ out) {
    extern __shared__ char sm[];
    gemm_core(ah, wo, out, nullptr, 0, smem_u32(sm),
              blockIdx.y * MT, blockIdx.x * NT);
}

// ============ Flash attention all-single-fp16: QK = Q·K (1 MMA), PV = P·V (1 MMA) ============
#define ATILE (128 * 128)          // 16KB
#define KVTILE (64 * 128)          // 8KB
#define KVSTAGE (2 * KVTILE)       // 16KB: K, V
#define Q_OFF 0
#define KV_OFF ATILE               // 16KB
#define ATTN_SMEM (ATILE + 2 * KVSTAGE)  // 48KB

__global__ void __launch_bounds__(256, 2)
attn_mma_kernel(const __half* __restrict__ Qh, const __half* __restrict__ Kh,
                const __half* __restrict__ Vh, __half* __restrict__ Oh) {
    extern __shared__ char sm[];
    const uint32_t smb = smem_u32(sm);

    const int tid = threadIdx.x;
    const int lane = tid & 31;
    const int wid = tid >> 5;
    const int qt = gridDim.x - 1 - blockIdx.x;
    const int h  = blockIdx.y;
    const int b  = blockIdx.z;

    const size_t base = (size_t)b * SEQ * EMB + (size_t)h * HDIM;
    const __half* qp = Qh + base;
    const __half* kp = Kh + base;
    const __half* vp = Vh + base;

    auto load_kv = [&](int s, int kt) {
        const __half* bases[2] = {kp, vp};
#pragma unroll
        for (int it = 0; it < 4; it++) {
            int idx = tid + it * 256;      // 0..1023
            int arr = idx >> 9;            // 0: K, 1: V
            int rc  = idx & 511;
            int row = rc >> 3;
            int ch  = rc & 7;
            uint32_t soff = smb + KV_OFF + s * KVSTAGE + arr * KVTILE
                          + row * 128 + ((ch ^ (row & 7)) * 16);
            CP_ASYNC16(soff, bases[arr] + (size_t)(kt * 64 + row) * EMB + ch * 8);
        }
        CP_COMMIT();
    };

    // group 0: Q tile (single)
#pragma unroll
    for (int it = 0; it < 4; it++) {
        int idx = tid + it * 256;      // 0..1023
        int row = idx >> 3;
        int ch  = idx & 7;
        uint32_t soff = smb + Q_OFF + row * 128 + ((ch ^ (row & 7)) * 16);
        CP_ASYNC16(soff, qp + (size_t)(qt * 128 + row) * EMB + ch * 8);
    }
    CP_COMMIT();

    const int ktmax = 2 * qt + 1;
    load_kv(0, 0);

    float o[8][4];
#pragma unroll
    for (int j = 0; j < 8; j++)
#pragma unroll
        for (int c = 0; c < 4; c++) o[j][c] = 0.f;
    float m0 = -1e30f, m1 = -1e30f, l0 = 0.f, l1 = 0.f;

    const float sscale = 0.125f;
    const int qrow0 = qt * 128 + wid * 16 + (lane >> 2);
    const uint32_t sq = smb + Q_OFF;

    for (int kt = 0; kt <= ktmax; kt++) {
        if (kt < ktmax) { load_kv((kt + 1) & 1, kt + 1); CP_WAIT1(); }
        else           { CP_WAIT0(); }
        __syncthreads();

        bool active = (kt * 64 <= qt * 128 + wid * 16 + 15);
        if (active) {
            const int s = kt & 1;
            const uint32_t sk = smb + KV_OFF + s * KVSTAGE;
            const uint32_t sv = sk + KVTILE;

            // ---- S = Q K^T ----
            float sc[8][4];
#pragma unroll
            for (int j = 0; j < 8; j++)
#pragma unroll
                for (int c = 0; c < 4; c++) sc[j][c] = 0.f;

#pragma unroll
            for (int ks = 0; ks < 4; ks++) {
                uint32_t af[4];
                {
                    int row = wid * 16 + (lane & 15);
                    int ch = ks * 2 + (lane >> 4);
                    uint32_t off = row * 128 + ((ch ^ (row & 7)) * 16);
                    LDSM_X4(af, sq + off);
                }
#pragma unroll
                for (int jp = 0; jp < 4; jp++) {
                    int j = jp * 2;
                    int row = (j + (lane >> 4)) * 8 + (lane & 7);
                    int ch = ks * 2 + ((lane >> 3) & 1);
                    uint32_t off = row * 128 + ((ch ^ (row & 7)) * 16);
                    uint32_t bf[4];
                    LDSM_X4(bf, sk + off);
                    MMA16816H(sc[j],     af, (&bf[0]));
                    MMA16816H(sc[j + 1], af, (&bf[2]));
                }
            }

            // ---- scale + causal mask ----
            bool diag = (kt * 64 + 63 > qt * 128 + wid * 16);
#pragma unroll
            for (int j = 0; j < 8; j++) {
                int col = kt * 64 + j * 8 + (lane & 3) * 2;
#pragma unroll
                for (int c = 0; c < 4; c++) {
                    float v = sc[j][c] * sscale;
                    if (diag) {
                        int cc = col + (c & 1);
                        int rr = qrow0 + ((c >= 2) ? 8 : 0);
                        if (cc > rr) v = -1e30f;
                    }
                    sc[j][c] = v;
                }
            }

            // ---- online softmax ----
            float mt0 = -1e30f, mt1 = -1e30f;
#pragma unroll
            for (int j = 0; j < 8; j++) {
                mt0 = fmaxf(mt0, fmaxf(sc[j][0], sc[j][1]));
                mt1 = fmaxf(mt1, fmaxf(sc[j][2], sc[j][3]));
            }
            mt0 = fmaxf(mt0, __shfl_xor_sync(0xffffffffu, mt0, 1));
            mt0 = fmaxf(mt0, __shfl_xor_sync(0xffffffffu, mt0, 2));
            mt1 = fmaxf(mt1, __shfl_xor_sync(0xffffffffu, mt1, 1));
            mt1 = fmaxf(mt1, __shfl_xor_sync(0xffffffffu, mt1, 2));

            float mn0 = fmaxf(m0, mt0), mn1 = fmaxf(m1, mt1);
            float corr0 = __expf(m0 - mn0), corr1 = __expf(m1 - mn1);

            float ps0 = 0.f, ps1 = 0.f;
#pragma unroll
            for (int j = 0; j < 8; j++) {
                float p0 = __expf(sc[j][0] - mn0);
                float p1 = __expf(sc[j][1] - mn0);
                float p2 = __expf(sc[j][2] - mn1);
                float p3 = __expf(sc[j][3] - mn1);
                sc[j][0] = p0; sc[j][1] = p1; sc[j][2] = p2; sc[j][3] = p3;
                ps0 += p0 + p1; ps1 += p2 + p3;
            }
            ps0 += __shfl_xor_sync(0xffffffffu, ps0, 1);
            ps0 += __shfl_xor_sync(0xffffffffu, ps0, 2);
            ps1 += __shfl_xor_sync(0xffffffffu, ps1, 1);
            ps1 += __shfl_xor_sync(0xffffffffu, ps1, 2);

            l0 = l0 * corr0 + ps0; m0 = mn0;
            l1 = l1 * corr1 + ps1; m1 = mn1;
#pragma unroll
            for (int j = 0; j < 8; j++) {
                o[j][0] *= corr0; o[j][1] *= corr0;
                o[j][2] *= corr1; o[j][3] *= corr1;
            }

            // ---- O += P V ----
#pragma unroll
            for (int ks = 0; ks < 4; ks++) {
                uint32_t ph[4];
                ph[0] = packh2(sc[2*ks][0],   sc[2*ks][1]);
                ph[1] = packh2(sc[2*ks][2],   sc[2*ks][3]);
                ph[2] = packh2(sc[2*ks+1][0], sc[2*ks+1][1]);
                ph[3] = packh2(sc[2*ks+1][2], sc[2*ks+1][3]);
#pragma unroll
                for (int j = 0; j < 4; j++) {
                    uint32_t bf[4];
                    int row = ks * 16 + (lane & 15);
                    int ch = j * 2 + (lane >> 4);
                    uint32_t off = row * 128 + ((ch ^ (row & 7)) * 16);
                    LDSM_X4T(bf, sv + off);
                    MMA16816H(o[2*j],     ph, (&bf[0]));
                    MMA16816H(o[2*j + 1], ph, (&bf[2]));
                }
            }
        }
        __syncthreads();
    }

    // ---- normalize + single-fp16 store (for Wo GEMM) ----
    float inv0 = 1.f / l0, inv1 = 1.f / l1;
    const int row0 = b * SEQ + qt * 128 + wid * 16 + (lane >> 2);
#pragma unroll
    for (int j = 0; j < 8; j++) {
        float a0 = o[j][0] * inv0, a1 = o[j][1] * inv0;
        float a2 = o[j][2] * inv1, a3 = o[j][3] * inv1;
        size_t off0 = (size_t)row0 * EMB + h * HDIM + j * 8 + (lane & 3) * 2;
        size_t off1 = off0 + (size_t)8 * EMB;
        *(uint32_t*)&Oh[off0] = packh2(a0, a1);
        *(uint32_t*)&Oh[off1] = packh2(a2, a3);
    }
}

// ======================= Scratch =======================
__device__ __half g_xh[TOK * EMB];
__device__ __half g_qh[TOK * EMB], g_kh[TOK * EMB], g_vh[TOK * EMB];
__device__ __half g_ah[TOK * EMB];
__device__ __half g_wq[EMB * EMB], g_wk[EMB * EMB], g_wv[EMB * EMB], g_wo[EMB * EMB];

extern "C" void kernel_launch(void* const* d_in, const int* in_sizes, int n_in,
                              void* d_out, int out_size) {
    const float* x  = (const float*)d_in[0];
    const float* Wq = (const float*)d_in[2];
    const float* Wk = (const float*)d_in[3];
    const float* Wv = (const float*)d_in[4];
    const float* Wo = (const float*)d_in[5];
    float* out = (float*)d_out;

    __half *xh, *qh, *kh, *vh, *ah, *wq, *wk, *wv, *wo;
    cudaGetSymbolAddress((void**)&xh, g_xh);
    cudaGetSymbolAddress((void**)&qh, g_qh);
    cudaGetSymbolAddress((void**)&kh, g_kh);
    cudaGetSymbolAddress((void**)&vh, g_vh);
    cudaGetSymbolAddress((void**)&ah, g_ah);
    cudaGetSymbolAddress((void**)&wq, g_wq);
    cudaGetSymbolAddress((void**)&wk, g_wk);
    cudaGetSymbolAddress((void**)&wv, g_wv);
    cudaGetSymbolAddress((void**)&wo, g_wo);

    static bool attrs_set = false;
    if (!attrs_set) {
        cudaFuncSetAttribute(gemm_qkv_kernel,
                             cudaFuncAttributeMaxDynamicSharedMemorySize, GEMM_SMEM);
        cudaFuncSetAttribute(gemm_o_kernel,
                             cudaFuncAttributeMaxDynamicSharedMemorySize, GEMM_SMEM);
        cudaFuncSetAttribute(attn_mma_kernel,
                             cudaFuncAttributeMaxDynamicSharedMemorySize, ATTN_SMEM);
        attrs_set = true;
    }

    const int XB = (TOK * EMB / 4 + 255) / 256;
    dim3 cvtGrid(XB, 5);
    cvt_all_kernel<<<cvtGrid, 256>>>(x, Wq, Wk, Wv, Wo, xh, wq, wk, wv, wo);

    dim3 qkvGrid(EMB / NT, TOK / MT, 3);   // (8, 32, 3)
    gemm_qkv_kernel<<<qkvGrid, 256, GEMM_SMEM>>>(xh, wq, wk, wv, qh, kh, vh);

    dim3 attnGrid(SEQ / 128, HEADS, BATCH);   // (16, 16, 2)
    attn_mma_kernel<<<attnGrid, 256, ATTN_SMEM>>>(qh, kh, vh, ah);

    dim3 oGrid(EMB / NT, TOK / MT);   // (8, 32)
    gemm_o_kernel<<<oGrid, 256, GEMM_SMEM>>>(ah, wo, out);
}